// round 13
// baseline (speedup 1.0000x reference)
#include <cuda_runtime.h>
#include <cuda_bf16.h>
#include <math_constants.h>
#include <stdint.h>

#define BATCH 4
#define NPIX 4096   // 64*64

// ---------------- scratch (device globals; no cudaMalloc allowed) ----------------
__device__ float g_buf1 [BATCH * 256 * NPIX];      // conv1 raw out (fp32)
__device__ float g_buf2 [BATCH * 256 * NPIX];      // conv2 raw out (fp32)
__device__ float g_xt0  [BATCH * 8  * 2 * NPIX * 8];   // conv1 input packed bf16 hi/lo
__device__ float g_xt1  [BATCH * 16 * 2 * NPIX * 8];   // conv2 input packed
__device__ float g_xt2  [BATCH * 16 * 2 * NPIX * 8];   // aspp  input packed
__device__ float g_br  [4 * BATCH * 64 * NPIX];
__device__ float g_q   [4 * BATCH * 64 * NPIX];    // plain q
__device__ float g_kf  [16 * 4096 * 128];          // K' fragment-paired tf32
__device__ float g_vf  [16 * 64 * 256 * 16];       // V  fragment-paired tf32
__device__ float g_pos [64 * NPIX];
__device__ float g_p1  [256 * 256];
__device__ float g_p2  [256 * 256];
__device__ float g_An  [6 * 256];
__device__ float g_Bn  [6 * 256];
__device__ float g_wt  [1327104];   // packed bf16 hi/lo conv weights

__device__ __forceinline__ uint32_t f2tf32(float f) {
    uint32_t u;
    asm("cvt.rna.tf32.f32 %0, %1;" : "=r"(u) : "f"(f));
    return u;
}
__device__ __forceinline__ float ex2f(float x) {
    float y;
    asm("ex2.approx.ftz.f32 %0, %1;" : "=f"(y) : "f"(x));
    return y;
}
__device__ __forceinline__ void mma8(float d[4], const uint32_t a[4],
                                     uint32_t b0, uint32_t b1) {
    asm volatile(
        "mma.sync.aligned.m16n8k8.row.col.f32.tf32.tf32.f32 "
        "{%0,%1,%2,%3},{%4,%5,%6,%7},{%8,%9},{%0,%1,%2,%3};"
        : "+f"(d[0]), "+f"(d[1]), "+f"(d[2]), "+f"(d[3])
        : "r"(a[0]), "r"(a[1]), "r"(a[2]), "r"(a[3]), "r"(b0), "r"(b1));
}
__device__ __forceinline__ void mma16(float d[4], const uint32_t a[4],
                                      uint32_t b0, uint32_t b1) {
    asm volatile(
        "mma.sync.aligned.m16n8k16.row.col.f32.bf16.bf16.f32 "
        "{%0,%1,%2,%3},{%4,%5,%6,%7},{%8,%9},{%0,%1,%2,%3};"
        : "+f"(d[0]), "+f"(d[1]), "+f"(d[2]), "+f"(d[3])
        : "r"(a[0]), "r"(a[1]), "r"(a[2]), "r"(a[3]), "r"(b0), "r"(b1));
}
__device__ __forceinline__ int ilv(int klo) { return (klo & 3) * 2 + (klo >> 2); }
__device__ __forceinline__ uint32_t pk2bf(float a, float b) {
    __nv_bfloat162 t = __floats2bfloat162_rn(a, b);
    return *reinterpret_cast<uint32_t*>(&t);
}
__device__ __forceinline__ float bfhi(float x) {
    return __bfloat162float(__float2bfloat16(x));
}

// ---------------- maxpool 2x2 -> packed bf16 hi/lo channel-pair layout ----------------
__global__ void maxpool_xt_kernel(const float* __restrict__ x, float* __restrict__ xt) {
    int idx = blockIdx.x * blockDim.x + threadIdx.x;
    if (idx >= BATCH * 64 * NPIX) return;
    int pix = idx & 4095, rest = idx >> 12;
    int cp = rest & 63, b = rest >> 6;
    int y = pix >> 6, xx = pix & 63;
    float v[2];
#pragma unroll
    for (int e = 0; e < 2; e++) {
        const float* src = x + ((long)(b * 128 + 2 * cp + e) * 128 + 2 * y) * 128 + 2 * xx;
        v[e] = fmaxf(fmaxf(src[0], src[1]), fmaxf(src[128], src[129]));
    }
    float h0 = bfhi(v[0]), h1 = bfhi(v[1]);
    int chunk = cp >> 3, j = cp & 7;
    long base = (((long)(b * 8 + chunk) * 2) * 4096 + pix) * 8 + ilv(j);
    uint32_t* out = (uint32_t*)xt;
    out[base]         = pk2bf(h0, h1);
    out[base + 32768] = pk2bf(v[0] - h0, v[1] - h1);
}

// ---------------- bnprep: raw fp32 [c][pix] -> relu(BN) -> packed bf16 hi/lo ----------------
__global__ void bnprep_xt_kernel(const float* __restrict__ in, float* __restrict__ xt,
                                 const float* __restrict__ A, const float* __restrict__ B) {
    int idx = blockIdx.x * blockDim.x + threadIdx.x;
    if (idx >= BATCH * 128 * NPIX) return;
    int pix = idx & 4095, rest = idx >> 12;
    int cp = rest & 127, b = rest >> 7;
    int c0 = 2 * cp;
    float v0 = fmaxf(in[((long)(b * 256 + c0)) * NPIX + pix] * A[c0] + B[c0], 0.f);
    float v1 = fmaxf(in[((long)(b * 256 + c0 + 1)) * NPIX + pix] * A[c0 + 1] + B[c0 + 1], 0.f);
    float h0 = bfhi(v0), h1 = bfhi(v1);
    int chunk = cp >> 3, j = cp & 7;
    long base = (((long)(b * 16 + chunk) * 2) * 4096 + pix) * 8 + ilv(j);
    uint32_t* out = (uint32_t*)xt;
    out[base]         = pk2bf(h0, h1);
    out[base + 32768] = pk2bf(v0 - h0, v1 - h1);
}

// ---------------- weight prep: OIHW -> [ocg64][chunk16ic][hi/lo][tap][ocl][8 words] ----------------
__global__ void wprep_kernel(const float* __restrict__ W, float* __restrict__ dst,
                             int Cin, int Cout) {
    int idx = blockIdx.x * 256 + threadIdx.x;
    int cp = Cin >> 1;
    int total = Cout * cp * 9;
    if (idx >= total) return;
    int tap = idx % 9;
    int rem = idx / 9;
    int jp  = rem % cp;
    int oc  = rem / cp;
    float w0 = W[((long)oc * Cin + 2 * jp) * 9 + tap];
    float w1 = W[((long)oc * Cin + 2 * jp + 1) * 9 + tap];
    float h0 = bfhi(w0), h1 = bfhi(w1);
    int ocg = oc >> 6, ocl = oc & 63, chunk = jp >> 3, j = jp & 7;
    int nch = Cin >> 4;
    long base = (long)(ocg * nch + chunk) * 9216;
    uint32_t* d = (uint32_t*)dst;
    d[base +        (tap * 64 + ocl) * 8 + ilv(j)] = pk2bf(h0, h1);
    d[base + 4608 + (tap * 64 + ocl) * 8 + ilv(j)] = pk2bf(w0 - h0, w1 - h1);
}

// ======== bf16 3-term tensor-core 3x3 dilated conv, 2-stage cp.async pipeline ========
#define TSW   8448
#define SINW  16896
#define WW    9216
#define STAGEW 26112
#define CSM   ((2 * STAGEW + 1024) * 4)
template<bool AS>
__global__ void __launch_bounds__(512, 1) conv_mma_kernel(
    const float* __restrict__ in, const float* __restrict__ wtbase,
    float* __restrict__ outbase, int Cin,
    float* __restrict__ p1base, float* __restrict__ p2base)
{
    extern __shared__ float sm[];
    float* sRS = sm + 2 * STAGEW;
    float* sRQ = sRS + 512;

    const int ytile = blockIdx.x;
    const int b     = blockIdx.z;
    const int nchunk = Cin >> 4;
    int dil, ocg, Cout;
    const float* wt;
    float* out;
    float *p1, *p2;
    if (AS) {
        int br = blockIdx.y;
        dil = 3 * (br + 1); ocg = 0; Cout = 64;
        wt  = wtbase + (long)br * 147456;
        out = outbase + ((long)br * BATCH + b) * 64 * NPIX;
        p1  = p1base + br * 8192;
        p2  = p2base + br * 8192;
    } else {
        dil = 1; ocg = blockIdx.y; Cout = gridDim.y * 64;
        wt  = wtbase + (long)ocg * nchunk * WW;
        out = outbase + (long)b * Cout * NPIX;
        p1  = p1base; p2 = p2base;
    }
    in += (long)b * nchunk * 65536;

    const int t = threadIdx.x, lane = t & 31, w = t >> 5;
    const int g = lane >> 2, tq = lane & 3;
    const int mwarp = w >> 3;
    const int yr    = (w >> 1) & 3;
    const int nh    = w & 1;
    const int y0    = ytile * 4;

    const uint32_t smb = (uint32_t)__cvta_generic_to_shared(sm);

    for (int i = t; i < SINW; i += 512) { sm[i] = 0.f; sm[STAGEW + i] = 0.f; }
    __syncthreads();

    auto issue = [&](int c, int s) {
        const uint32_t stb = smb + (uint32_t)(s * STAGEW * 4);
        const float4* ws = (const float4*)(wt + (long)c * WW);
        const uint32_t swu = stb + (uint32_t)(SINW * 4);
        for (int i = t; i < 2304; i += 512)
            asm volatile("cp.async.cg.shared.global [%0], [%1], 16;\n"
                         :: "r"(swu + i * 16), "l"(ws + i));
#pragma unroll
        for (int e = t; e < 3072; e += 512) {
            int fx  = e & 127;
            int r   = e >> 7;
            int term = r / 12;
            int r2   = r - term * 12;
            int ky = r2 >> 2, yri = r2 & 3;
            int ry = y0 + yri + (ky - 1) * dil;
            int ok = (ry >= 0 && ry < 64);
            uint32_t dst = stb + (uint32_t)((term * TSW + (ky * 4 + yri) * 704 + 96) * 4 + fx * 16);
            const float4* src = (const float4*)(in + ((long)(c * 2 + term) * 4096 +
                                                      (ok ? ry : 0) * 64) * 8) + fx;
            int ssz = ok ? 16 : 0;
            asm volatile("cp.async.cg.shared.global [%0], [%1], 16, %2;\n"
                         :: "r"(dst), "l"(src), "r"(ssz));
        }
        asm volatile("cp.async.commit_group;\n");
    };

    float acc[2][4][4];
#pragma unroll
    for (int mf = 0; mf < 2; mf++)
#pragma unroll
        for (int nt = 0; nt < 4; nt++)
#pragma unroll
            for (int c = 0; c < 4; c++) acc[mf][nt][c] = 0.f;

    issue(0, 0);

    for (int chunk = 0; chunk < nchunk; chunk++) {
        const int s = chunk & 1;
        if (chunk + 1 < nchunk) {
            issue(chunk + 1, s ^ 1);
            asm volatile("cp.async.wait_group 1;\n" ::: "memory");
        } else {
            asm volatile("cp.async.wait_group 0;\n" ::: "memory");
        }
        __syncthreads();

        const uint32_t* sIn = (const uint32_t*)sm + s * STAGEW;
        const uint32_t* sW  = sIn + SINW;

#pragma unroll
        for (int tap = 0; tap < 9; tap++) {
            const int ky = tap / 3, kx = tap % 3;
            const uint32_t* wb = sW + (tap * 64 + mwarp * 32 + g) * 8 + 2 * tq;
            uint2 h0  = *(const uint2*)(wb);
            uint2 h0b = *(const uint2*)(wb + 64);
            uint2 h1  = *(const uint2*)(wb + 128);
            uint2 h1b = *(const uint2*)(wb + 192);
            uint2 l0  = *(const uint2*)(wb + 4608);
            uint2 l0b = *(const uint2*)(wb + 4672);
            uint2 l1  = *(const uint2*)(wb + 4736);
            uint2 l1b = *(const uint2*)(wb + 4800);
            uint32_t aH0[4] = {h0.x, h0b.x, h0.y, h0b.y};
            uint32_t aH1[4] = {h1.x, h1b.x, h1.y, h1b.y};
            uint32_t aL0[4] = {l0.x, l0b.x, l0.y, l0b.y};
            uint32_t aL1[4] = {l1.x, l1b.x, l1.y, l1b.y};
            const int rowoff = (ky * 4 + yr) * 704 +
                               (12 + nh * 32 + g + (kx - 1) * dil) * 8 + 2 * tq;
#pragma unroll
            for (int nt = 0; nt < 4; nt++) {
                uint2 bh = *(const uint2*)(sIn + rowoff + nt * 64);
                uint2 bl = *(const uint2*)(sIn + TSW + rowoff + nt * 64);
                mma16(acc[0][nt], aH0, bh.x, bh.y);
                mma16(acc[0][nt], aL0, bh.x, bh.y);
                mma16(acc[0][nt], aH0, bl.x, bl.y);
                mma16(acc[1][nt], aH1, bh.x, bh.y);
                mma16(acc[1][nt], aL1, bh.x, bh.y);
                mma16(acc[1][nt], aH1, bl.x, bl.y);
            }
        }
        __syncthreads();
    }

    // ---- epilogue: store + BN partials ----
    float s_[2][2] = {{0.f, 0.f}, {0.f, 0.f}};
    float q_[2][2] = {{0.f, 0.f}, {0.f, 0.f}};
    const int ocb = ocg * 64 + mwarp * 32;
#pragma unroll
    for (int mf = 0; mf < 2; mf++) {
        int oc = ocb + mf * 16 + g;
#pragma unroll
        for (int nt = 0; nt < 4; nt++) {
            int gx = (y0 + yr) * 64 + nh * 32 + nt * 8 + 2 * tq;
            float c0 = acc[mf][nt][0], c1 = acc[mf][nt][1];
            float c2 = acc[mf][nt][2], c3 = acc[mf][nt][3];
            out[(long)oc * NPIX + gx]           = c0;
            out[(long)oc * NPIX + gx + 1]       = c1;
            out[(long)(oc + 8) * NPIX + gx]     = c2;
            out[(long)(oc + 8) * NPIX + gx + 1] = c3;
            s_[mf][0] += c0 + c1; q_[mf][0] += c0 * c0 + c1 * c1;
            s_[mf][1] += c2 + c3; q_[mf][1] += c2 * c2 + c3 * c3;
        }
    }
#pragma unroll
    for (int mf = 0; mf < 2; mf++)
#pragma unroll
        for (int ro = 0; ro < 2; ro++) {
            float a = s_[mf][ro], qq = q_[mf][ro];
            a  += __shfl_xor_sync(0xffffffffu, a, 1);
            qq += __shfl_xor_sync(0xffffffffu, qq, 1);
            a  += __shfl_xor_sync(0xffffffffu, a, 2);
            qq += __shfl_xor_sync(0xffffffffu, qq, 2);
            if (tq == 0) {
                sRS[w * 32 + mf * 16 + ro * 8 + g] = a;
                sRQ[w * 32 + mf * 16 + ro * 8 + g] = qq;
            }
        }
    __syncthreads();
    if (t < 64) {
        int mw = t >> 5, cl = t & 31;
        float a = 0.f, qq = 0.f;
#pragma unroll
        for (int j = 0; j < 8; j++) {
            a  += sRS[(mw * 8 + j) * 32 + cl];
            qq += sRQ[(mw * 8 + j) * 32 + cl];
        }
        int slot = b * 16 + ytile;
        p1[slot * Cout + ocg * 64 + t] = a;
        p2[slot * Cout + ocg * 64 + t] = qq;
    }
}

// ---------------- BN finalize ----------------
__global__ void finalize_kernel(const float* __restrict__ p1, const float* __restrict__ p2,
                                const float* __restrict__ g, const float* __restrict__ be,
                                float* __restrict__ A, float* __restrict__ B,
                                int C, int nslots) {
    const int c = blockIdx.x, t = threadIdx.x;
    float s = 0.f, q = 0.f;
    for (int slot = t; slot < nslots; slot += 128) {
        s += p1[slot * C + c];
        q += p2[slot * C + c];
    }
    __shared__ float rs[4], rq[4];
#pragma unroll
    for (int off = 16; off; off >>= 1) {
        s += __shfl_down_sync(0xffffffffu, s, off);
        q += __shfl_down_sync(0xffffffffu, q, off);
    }
    int lane = t & 31, wp = t >> 5;
    if (!lane) { rs[wp] = s; rq[wp] = q; }
    __syncthreads();
    if (t == 0) {
        s = rs[0] + rs[1] + rs[2] + rs[3];
        q = rq[0] + rq[1] + rq[2] + rq[3];
        const float inv = 1.f / (float)(BATCH * NPIX);
        float mean = s * inv;
        float var  = q * inv - mean * mean;
        float a = g[c] * rsqrtf(var + 1e-5f);
        A[c] = a;
        B[c] = be[c] - mean * a;
    }
}

// ---------------- 1x1 conv Cout=64 with input-BN + stats (aspp1, exact fp32) ----------------
__global__ void __launch_bounds__(256) conv1x1_bn_kernel(
    const float* __restrict__ in, const float* __restrict__ w,
    float* __restrict__ out, int Cin,
    const float* __restrict__ Abn, const float* __restrict__ Bbn,
    float* __restrict__ p1, float* __restrict__ p2)
{
    const int p0 = blockIdx.x * 64;
    const int b  = blockIdx.z;
    in  += (long)b * Cin * NPIX;
    out += (long)b * 64  * NPIX;
    const int t = threadIdx.x, tx = t & 15, ty = t >> 4;

    __shared__ float sW [16 * 68];
    __shared__ float sIn[16 * 64];

    float acc[4][4];
#pragma unroll
    for (int r = 0; r < 4; r++)
#pragma unroll
        for (int c = 0; c < 4; c++) acc[r][c] = 0.f;

    for (int ic0 = 0; ic0 < Cin; ic0 += 16) {
        __syncthreads();
        for (int idx = t; idx < 1024; idx += 256) {
            int ic = idx & 15, oc = idx >> 4;
            sW[ic * 68 + oc] = w[(long)oc * Cin + ic0 + ic];
        }
        for (int idx = t; idx < 1024; idx += 256) {
            int ic = idx >> 6, px = idx & 63;
            int c = ic0 + ic;
            float v = in[c * NPIX + p0 + px];
            sIn[idx] = fmaxf(v * Abn[c] + Bbn[c], 0.f);
        }
        __syncthreads();
#pragma unroll
        for (int ic = 0; ic < 16; ic++) {
            float4 a  = *(const float4*)(sW  + ic * 68 + ty * 4);
            float4 xv = *(const float4*)(sIn + ic * 64 + tx * 4);
            float av[4] = {a.x, a.y, a.z, a.w};
            float xa[4] = {xv.x, xv.y, xv.z, xv.w};
#pragma unroll
            for (int r = 0; r < 4; r++)
#pragma unroll
                for (int c = 0; c < 4; c++) acc[r][c] += av[r] * xa[c];
        }
    }
    float sums[4], sqs[4];
#pragma unroll
    for (int r = 0; r < 4; r++) {
        float s = 0.f, q = 0.f;
        float* op = out + (long)(ty * 4 + r) * NPIX + p0 + tx * 4;
#pragma unroll
        for (int c = 0; c < 4; c++) {
            float v = acc[r][c];
            op[c] = v; s += v; q += v * v;
        }
        sums[r] = s; sqs[r] = q;
    }
#pragma unroll
    for (int r = 0; r < 4; r++) {
        float a = sums[r], q = sqs[r];
#pragma unroll
        for (int off = 1; off < 16; off <<= 1) {
            a += __shfl_xor_sync(0xffffffffu, a, off);
            q += __shfl_xor_sync(0xffffffffu, q, off);
        }
        if (tx == 0) {
            int c = ty * 4 + r;
            int slot = b * 64 + blockIdx.x;
            p1[slot * 64 + c] = a;
            p2[slot * 64 + c] = q;
        }
    }
}

// ---------------- fused q/k/v 1x1 projections -> q plain + K'/V fragment layouts ----------------
__global__ void __launch_bounds__(256) qkv_kernel(
    const float* __restrict__ brin,
    const float* __restrict__ wq, const float* __restrict__ bq,
    const float* __restrict__ wk, const float* __restrict__ bk,
    const float* __restrict__ wv, const float* __restrict__ bv,
    float* __restrict__ qo, float* __restrict__ kf, float* __restrict__ vf,
    const float* __restrict__ Abase, const float* __restrict__ Bbase)
{
    const int p0  = blockIdx.x * 64;
    const int img = blockIdx.z;
    const int br  = img >> 2;
    const long ib = (long)img * 64 * NPIX;
    const float* A  = Abase + (2 + br) * 256;
    const float* Bb = Bbase + (2 + br) * 256;
    const int t = threadIdx.x, tx = t & 15, ty = t >> 4;

    float* kfp = kf + (long)img * 524288;
    float* vfp = vf + (long)img * 262144;

    __shared__ float sW [3 * 16 * 64];
    __shared__ float sIn[16 * 64];

    float acc[3][4][4];
#pragma unroll
    for (int m = 0; m < 3; m++)
#pragma unroll
        for (int r = 0; r < 4; r++)
#pragma unroll
            for (int c = 0; c < 4; c++) acc[m][r][c] = 0.f;

    for (int ic0 = 0; ic0 < 64; ic0 += 16) {
        __syncthreads();
        for (int i = t; i < 1024; i += 256) {
            int ic = i >> 6, px = i & 63;
            int c = ic0 + ic;
            float v = brin[ib + (long)c * NPIX + p0 + px];
            sIn[i] = fmaxf(v * A[c] + Bb[c], 0.f);
        }
        for (int i = t; i < 3072; i += 256) {
            int m = i >> 10, r = i & 1023;
            int ic = r & 15, oc = r >> 4;
            const float* wm = (m == 0) ? wq : ((m == 1) ? wk : wv);
            sW[m * 1024 + ic * 64 + oc] = wm[oc * 64 + ic0 + ic];
        }
        __syncthreads();
#pragma unroll
        for (int ic = 0; ic < 16; ic++) {
            float4 xv = *(const float4*)(sIn + ic * 64 + tx * 4);
            float xa[4] = {xv.x, xv.y, xv.z, xv.w};
#pragma unroll
            for (int m = 0; m < 3; m++) {
                float4 a = *(const float4*)(sW + m * 1024 + ic * 64 + ty * 4);
                float av[4] = {a.x, a.y, a.z, a.w};
#pragma unroll
                for (int r = 0; r < 4; r++)
#pragma unroll
                    for (int c = 0; c < 4; c++) acc[m][r][c] += av[r] * xa[c];
            }
        }
    }
    const float* bs[3] = {bq, bk, bv};
#pragma unroll
    for (int m = 0; m < 3; m++) {
#pragma unroll
        for (int r = 0; r < 4; r++) {
            int oc = ty * 4 + r;
            float bb = bs[m][oc];
#pragma unroll
            for (int ci = 0; ci < 4; ci++) {
                int j = p0 + tx * 4 + ci;
                float val = acc[m][r][ci] + bb;
                if (m == 0) {
                    qo[ib + (long)oc * NPIX + j] = val;
                    int kk = 64 + oc, ks = kk >> 3, klo = kk & 7;
                    int slot = (ks >> 1) * 16 + (klo & 3) * 4 + (ks & 1) * 2 + (klo >> 2);
                    kfp[j * 128 + slot] = __uint_as_float(f2tf32(val));
                } else if (m == 1) {
                    int kk = oc, ks = kk >> 3, klo = kk & 7;
                    int slot = (ks >> 1) * 16 + (klo & 3) * 4 + (ks & 1) * 2 + (klo >> 2);
                    kfp[j * 128 + slot] = __uint_as_float(f2tf32(val));
                } else {
                    int ksv = j >> 3, jlo = j & 7;
                    int slot = (jlo & 3) * 4 + (ksv & 1) * 2 + (jlo >> 2);
                    vfp[(oc * 256 + (ksv >> 1)) * 16 + slot] = __uint_as_float(f2tf32(val));
                }
            }
        }
    }
}

// ---------------- pos table ----------------
__global__ void pos_kernel(const float* __restrict__ rh, const float* __restrict__ rw) {
    int idx = blockIdx.x * blockDim.x + threadIdx.x;
    if (idx >= 64 * NPIX) return;
    int d = idx >> 12, n = idx & 4095, a = n >> 6, bb = n & 63;
    g_pos[idx] = rh[d * 64 + bb] + rw[d * 64 + a];
}

// ================= fragment-direct tf32 flash attention (fine-grained CTAs) =================
// 128 threads = 4 warps, i-tile 64 rows; per-warp code identical to the 256-thr version.
#define FLASH4_SMEM (4096 * 4)
#define LOG2E 1.44269504088896f

__global__ void __launch_bounds__(128) flash_mma_kernel(
    const float* __restrict__ qg, const float* __restrict__ kf,
    const float* __restrict__ vf, float* __restrict__ outg)
{
    extern __shared__ uint32_t smu[];
    uint32_t* sP = smu;   // [warp 4][ks 8][i 16][8 interleaved]

    const int i0 = blockIdx.x * 64;
    const int b  = blockIdx.y, br = blockIdx.z;
    const int img = br * BATCH + b;
    const float* q = qg + (long)img * 64 * NPIX;
    const uint4* KF = (const uint4*)(kf + (long)img * 524288);
    const uint4* VF = (const uint4*)(vf + (long)img * 262144);
    float* outp = outg + (long)(b * 256 + br * 64) * NPIX;

    const int t = threadIdx.x;
    const int lane = t & 31, w = t >> 5;      // w in 0..3
    const int g = lane >> 2, tq = lane & 3;

    uint32_t Qf[16][4];
    {
        int i_r = i0 + w * 16 + g;
#pragma unroll
        for (int ks = 0; ks < 16; ks++) {
            int kc = ks * 8 + tq;
            const float* s0 = (kc < 64)     ? (q + kc * NPIX)       : (g_pos + (kc - 64) * NPIX);
            const float* s1 = (kc + 4 < 64) ? (q + (kc + 4) * NPIX) : (g_pos + (kc - 60) * NPIX);
            Qf[ks][0] = f2tf32(s0[i_r] * LOG2E);
            Qf[ks][1] = f2tf32(s0[i_r + 8] * LOG2E);
            Qf[ks][2] = f2tf32(s1[i_r] * LOG2E);
            Qf[ks][3] = f2tf32(s1[i_r + 8] * LOG2E);
        }
    }

    float Oa[8][4];
#pragma unroll
    for (int nt = 0; nt < 8; nt++)
#pragma unroll
        for (int c = 0; c < 4; c++) Oa[nt][c] = 0.f;
    float m0 = -CUDART_INF_F, m1 = -CUDART_INF_F, l0 = 0.f, l1 = 0.f;

    const int p00 = ((2 * tq) & 3) * 2 + (tq >> 1);
    const int p01 = ((2 * tq + 1) & 3) * 2 + ((2 * tq + 1) >> 2);
    const int pb  = w * 1024 + g * 8;

    for (int j0 = 0; j0 < NPIX; j0 += 64) {
        float Sa[8][4];
#pragma unroll
        for (int nt = 0; nt < 8; nt++)
#pragma unroll
            for (int c = 0; c < 4; c++) Sa[nt][c] = 0.f;
#pragma unroll
        for (int kp = 0; kp < 8; kp++) {
#pragma unroll
            for (int nt = 0; nt < 8; nt++) {
                uint4 kb = KF[(j0 + nt * 8 + g) * 32 + kp * 4 + tq];
                mma8(Sa[nt], Qf[2 * kp],     kb.x, kb.y);
                mma8(Sa[nt], Qf[2 * kp + 1], kb.z, kb.w);
            }
        }

        float mx0 = -CUDART_INF_F, mx1 = -CUDART_INF_F;
#pragma unroll
        for (int nt = 0; nt < 8; nt++) {
            mx0 = fmaxf(mx0, fmaxf(Sa[nt][0], Sa[nt][1]));
            mx1 = fmaxf(mx1, fmaxf(Sa[nt][2], Sa[nt][3]));
        }
        mx0 = fmaxf(mx0, __shfl_xor_sync(0xffffffffu, mx0, 1));
        mx0 = fmaxf(mx0, __shfl_xor_sync(0xffffffffu, mx0, 2));
        mx1 = fmaxf(mx1, __shfl_xor_sync(0xffffffffu, mx1, 1));
        mx1 = fmaxf(mx1, __shfl_xor_sync(0xffffffffu, mx1, 2));
        float mn0 = fmaxf(m0, mx0), mn1 = fmaxf(m1, mx1);
        float al0 = ex2f(m0 - mn0), al1 = ex2f(m1 - mn1);

        float su0 = 0.f, su1 = 0.f;
#pragma unroll
        for (int nt = 0; nt < 8; nt++) {
            float e00 = ex2f(Sa[nt][0] - mn0);
            float e01 = ex2f(Sa[nt][1] - mn0);
            float e10 = ex2f(Sa[nt][2] - mn1);
            float e11 = ex2f(Sa[nt][3] - mn1);
            su0 += e00 + e01; su1 += e10 + e11;
            sP[pb + nt * 128 + p00]      = f2tf32(e00);
            sP[pb + nt * 128 + p01]      = f2tf32(e01);
            sP[pb + nt * 128 + 64 + p00] = f2tf32(e10);
            sP[pb + nt * 128 + 64 + p01] = f2tf32(e11);
        }
        su0 += __shfl_xor_sync(0xffffffffu, su0, 1);
        su0 += __shfl_xor_sync(0xffffffffu, su0, 2);
        su1 += __shfl_xor_sync(0xffffffffu, su1, 1);
        su1 += __shfl_xor_sync(0xffffffffu, su1, 2);
        l0 = l0 * al0 + su0; l1 = l1 * al1 + su1;
        m0 = mn0; m1 = mn1;
#pragma unroll
        for (int nt = 0; nt < 8; nt++) {
            Oa[nt][0] *= al0; Oa[nt][1] *= al0;
            Oa[nt][2] *= al1; Oa[nt][3] *= al1;
        }
        __syncwarp();

#pragma unroll
        for (int kpl = 0; kpl < 4; kpl++) {
            const uint32_t* ape = &sP[w * 1024 + (2 * kpl) * 128 + g * 8 + 2 * tq];
            uint2 e02 = *(const uint2*)ape;
            uint2 e13 = *(const uint2*)(ape + 64);
            uint2 o02 = *(const uint2*)(ape + 128);
            uint2 o13 = *(const uint2*)(ape + 192);
            uint32_t ae[4] = {e02.x, e13.x, e02.y, e13.y};
            uint32_t ao[4] = {o02.x, o13.x, o02.y, o13.y};
#pragma unroll
            for (int nt = 0; nt < 8; nt++) {
                uint4 vb = VF[((nt * 8 + g) * 256 + (j0 >> 4) + kpl) * 4 + tq];
                mma8(Oa[nt], ae, vb.x, vb.y);
                mma8(Oa[nt], ao, vb.z, vb.w);
            }
        }
        __syncwarp();
    }

    float inv0 = 1.f / l0, inv1 = 1.f / l1;
    int pix = i0 + w * 16 + g;
#pragma unroll
    for (int nt = 0; nt < 8; nt++) {
        int d0 = nt * 8 + 2 * tq;
        outp[(long)d0 * NPIX + pix]           = Oa[nt][0] * inv0;
        outp[(long)(d0 + 1) * NPIX + pix]     = Oa[nt][1] * inv0;
        outp[(long)d0 * NPIX + pix + 8]       = Oa[nt][2] * inv1;
        outp[(long)(d0 + 1) * NPIX + pix + 8] = Oa[nt][3] * inv1;
    }
}

// ---------------- host orchestration ----------------
extern "C" void kernel_launch(void* const* d_in, const int* in_sizes, int n_in,
                              void* d_out, int out_size) {
    const float* x      = (const float*)d_in[0];
    const float* dc_w1  = (const float*)d_in[1];
    const float* dc_g1  = (const float*)d_in[3];
    const float* dc_be1 = (const float*)d_in[4];
    const float* dc_w2  = (const float*)d_in[5];
    const float* dc_g2  = (const float*)d_in[7];
    const float* dc_be2 = (const float*)d_in[8];
    const float* aw[4]  = {(const float*)d_in[9],  (const float*)d_in[12],
                           (const float*)d_in[15], (const float*)d_in[18]};
    const float* ag[4]  = {(const float*)d_in[10], (const float*)d_in[13],
                           (const float*)d_in[16], (const float*)d_in[19]};
    const float* ab[4]  = {(const float*)d_in[11], (const float*)d_in[14],
                           (const float*)d_in[17], (const float*)d_in[20]};
    const float* wq = (const float*)d_in[21]; const float* bq = (const float*)d_in[22];
    const float* wk = (const float*)d_in[23]; const float* bk = (const float*)d_in[24];
    const float* wv = (const float*)d_in[25]; const float* bv = (const float*)d_in[26];
    const float* rel_h = (const float*)d_in[27];
    const float* rel_w = (const float*)d_in[28];

    float *buf1, *buf2, *xt0, *xt1, *xt2, *brb, *qb, *kfb, *vfb;
    float *p1, *p2, *An, *Bn, *wt;
    cudaGetSymbolAddress((void**)&buf1, g_buf1);
    cudaGetSymbolAddress((void**)&buf2, g_buf2);
    cudaGetSymbolAddress((void**)&xt0,  g_xt0);
    cudaGetSymbolAddress((void**)&xt1,  g_xt1);
    cudaGetSymbolAddress((void**)&xt2,  g_xt2);
    cudaGetSymbolAddress((void**)&brb,  g_br);
    cudaGetSymbolAddress((void**)&qb,   g_q);
    cudaGetSymbolAddress((void**)&kfb,  g_kf);
    cudaGetSymbolAddress((void**)&vfb,  g_vf);
    cudaGetSymbolAddress((void**)&p1,   g_p1);
    cudaGetSymbolAddress((void**)&p2,   g_p2);
    cudaGetSymbolAddress((void**)&An,   g_An);
    cudaGetSymbolAddress((void**)&Bn,   g_Bn);
    cudaGetSymbolAddress((void**)&wt,   g_wt);

    float* wt1 = wt;                  // conv1: 294912
    float* wt2 = wt + 294912;         // conv2: 589824
    float* wtA = wt + 884736;         // aspp:  3 x 147456

    cudaFuncSetAttribute((const void*)conv_mma_kernel<false>,
                         cudaFuncAttributeMaxDynamicSharedMemorySize, CSM);
    cudaFuncSetAttribute((const void*)conv_mma_kernel<true>,
                         cudaFuncAttributeMaxDynamicSharedMemorySize, CSM);
    cudaFuncSetAttribute((const void*)flash_mma_kernel,
                         cudaFuncAttributeMaxDynamicSharedMemorySize, FLASH4_SMEM);

    // weight prep (bf16 hi/lo, fragment-packed)
    wprep_kernel<<<(256 * 64 * 9 + 255) / 256, 256>>>(dc_w1, wt1, 128, 256);
    wprep_kernel<<<(256 * 128 * 9 + 255) / 256, 256>>>(dc_w2, wt2, 256, 256);
    for (int i = 0; i < 3; i++)
        wprep_kernel<<<(64 * 128 * 9 + 255) / 256, 256>>>(
            aw[i + 1], wtA + (long)i * 147456, 256, 64);

    // mpconv
    maxpool_xt_kernel<<<(BATCH * 64 * NPIX + 255) / 256, 256>>>(x, xt0);
    conv_mma_kernel<false><<<dim3(16, 4, BATCH), 512, CSM>>>(
        xt0, wt1, buf1, 128, p1, p2);
    finalize_kernel<<<256, 128>>>(p1, p2, dc_g1, dc_be1, An + 0, Bn + 0, 256, 64);
    bnprep_xt_kernel<<<(BATCH * 128 * NPIX + 255) / 256, 256>>>(buf1, xt1, An + 0, Bn + 0);
    conv_mma_kernel<false><<<dim3(16, 4, BATCH), 512, CSM>>>(
        xt1, wt2, buf2, 256, p1, p2);
    finalize_kernel<<<256, 128>>>(p1, p2, dc_g2, dc_be2, An + 256, Bn + 256, 256, 64);
    bnprep_xt_kernel<<<(BATCH * 128 * NPIX + 255) / 256, 256>>>(buf2, xt2, An + 256, Bn + 256);

    // ASPP dilated branches fused; 1x1 branch exact
    conv_mma_kernel<true><<<dim3(16, 3, BATCH), 512, CSM>>>(
        xt2, wtA, brb + (long)BATCH * 64 * NPIX, 256, p1, p2);
    for (int i = 0; i < 3; i++)
        finalize_kernel<<<64, 128>>>(p1 + i * 8192, p2 + i * 8192, ag[i + 1], ab[i + 1],
                                     An + (3 + i) * 256, Bn + (3 + i) * 256, 64, 64);
    conv1x1_bn_kernel<<<dim3(64, 1, BATCH), 256>>>(
        buf2, aw[0], brb, 256, An + 256, Bn + 256, p1 + 32768, p2 + 32768);
    finalize_kernel<<<64, 128>>>(p1 + 32768, p2 + 32768, ag[0], ab[0],
                                 An + 2 * 256, Bn + 2 * 256, 64, 256);

    // fused qkv + pos
    qkv_kernel<<<dim3(64, 1, 16), 256>>>(brb, wq, bq, wk, bk, wv, bv,
                                         qb, kfb, vfb, An, Bn);
    pos_kernel<<<(64 * NPIX + 255) / 256, 256>>>(rel_h, rel_w);

    // fine-grained flash attention -> concat output
    flash_mma_kernel<<<dim3(64, BATCH, 4), 128, FLASH4_SMEM>>>(
        qb, kfb, vfb, (float*)d_out);
}

// round 14
// speedup vs baseline: 1.5109x; 1.5109x over previous
#include <cuda_runtime.h>
#include <cuda_bf16.h>
#include <cuda_fp16.h>
#include <math_constants.h>
#include <stdint.h>

#define BATCH 4
#define NPIX 4096   // 64*64

// ---------------- scratch (device globals; no cudaMalloc allowed) ----------------
__device__ float g_buf1 [BATCH * 256 * NPIX];      // conv1 raw out (fp32)
__device__ float g_buf2 [BATCH * 256 * NPIX];      // conv2 raw out (fp32)
__device__ float g_xt0  [BATCH * 8  * 2 * NPIX * 8];   // conv1 input packed bf16 hi/lo
__device__ float g_xt1  [BATCH * 16 * 2 * NPIX * 8];   // conv2 input packed
__device__ float g_xt2  [BATCH * 16 * 2 * NPIX * 8];   // aspp  input packed
__device__ float g_br  [4 * BATCH * 64 * NPIX];
__device__ float g_q   [4 * BATCH * 64 * NPIX];    // plain q
__device__ float g_kf  [16 * 4096 * 64];           // K' packed fp16 words
__device__ float g_vf  [16 * 64 * 256 * 8];        // V  packed fp16 words
__device__ float g_pos [64 * NPIX];
__device__ float g_p1  [256 * 256];
__device__ float g_p2  [256 * 256];
__device__ float g_An  [6 * 256];
__device__ float g_Bn  [6 * 256];
__device__ float g_wt  [1327104];   // packed bf16 hi/lo conv weights

__device__ __forceinline__ float ex2f(float x) {
    float y;
    asm("ex2.approx.ftz.f32 %0, %1;" : "=f"(y) : "f"(x));
    return y;
}
__device__ __forceinline__ void mma16(float d[4], const uint32_t a[4],
                                      uint32_t b0, uint32_t b1) {
    asm volatile(
        "mma.sync.aligned.m16n8k16.row.col.f32.bf16.bf16.f32 "
        "{%0,%1,%2,%3},{%4,%5,%6,%7},{%8,%9},{%0,%1,%2,%3};"
        : "+f"(d[0]), "+f"(d[1]), "+f"(d[2]), "+f"(d[3])
        : "r"(a[0]), "r"(a[1]), "r"(a[2]), "r"(a[3]), "r"(b0), "r"(b1));
}
__device__ __forceinline__ void mma16h(float d[4], const uint32_t a[4],
                                       uint32_t b0, uint32_t b1) {
    asm volatile(
        "mma.sync.aligned.m16n8k16.row.col.f32.f16.f16.f32 "
        "{%0,%1,%2,%3},{%4,%5,%6,%7},{%8,%9},{%0,%1,%2,%3};"
        : "+f"(d[0]), "+f"(d[1]), "+f"(d[2]), "+f"(d[3])
        : "r"(a[0]), "r"(a[1]), "r"(a[2]), "r"(a[3]), "r"(b0), "r"(b1));
}
__device__ __forceinline__ int ilv(int klo) { return (klo & 3) * 2 + (klo >> 2); }
__device__ __forceinline__ uint32_t pk2bf(float a, float b) {
    __nv_bfloat162 t = __floats2bfloat162_rn(a, b);
    return *reinterpret_cast<uint32_t*>(&t);
}
__device__ __forceinline__ uint32_t pk2h(float a, float b) {
    __half2 t = __floats2half2_rn(a, b);
    return *reinterpret_cast<uint32_t*>(&t);
}
__device__ __forceinline__ float bfhi(float x) {
    return __bfloat162float(__float2bfloat16(x));
}

// ---------------- maxpool 2x2 -> packed bf16 hi/lo channel-pair layout ----------------
__global__ void maxpool_xt_kernel(const float* __restrict__ x, float* __restrict__ xt) {
    int idx = blockIdx.x * blockDim.x + threadIdx.x;
    if (idx >= BATCH * 64 * NPIX) return;
    int pix = idx & 4095, rest = idx >> 12;
    int cp = rest & 63, b = rest >> 6;
    int y = pix >> 6, xx = pix & 63;
    float v[2];
#pragma unroll
    for (int e = 0; e < 2; e++) {
        const float* src = x + ((long)(b * 128 + 2 * cp + e) * 128 + 2 * y) * 128 + 2 * xx;
        v[e] = fmaxf(fmaxf(src[0], src[1]), fmaxf(src[128], src[129]));
    }
    float h0 = bfhi(v[0]), h1 = bfhi(v[1]);
    int chunk = cp >> 3, j = cp & 7;
    long base = (((long)(b * 8 + chunk) * 2) * 4096 + pix) * 8 + ilv(j);
    uint32_t* out = (uint32_t*)xt;
    out[base]         = pk2bf(h0, h1);
    out[base + 32768] = pk2bf(v[0] - h0, v[1] - h1);
}

// ---------------- bnprep: raw fp32 [c][pix] -> relu(BN) -> packed bf16 hi/lo ----------------
__global__ void bnprep_xt_kernel(const float* __restrict__ in, float* __restrict__ xt,
                                 const float* __restrict__ A, const float* __restrict__ B) {
    int idx = blockIdx.x * blockDim.x + threadIdx.x;
    if (idx >= BATCH * 128 * NPIX) return;
    int pix = idx & 4095, rest = idx >> 12;
    int cp = rest & 127, b = rest >> 7;
    int c0 = 2 * cp;
    float v0 = fmaxf(in[((long)(b * 256 + c0)) * NPIX + pix] * A[c0] + B[c0], 0.f);
    float v1 = fmaxf(in[((long)(b * 256 + c0 + 1)) * NPIX + pix] * A[c0 + 1] + B[c0 + 1], 0.f);
    float h0 = bfhi(v0), h1 = bfhi(v1);
    int chunk = cp >> 3, j = cp & 7;
    long base = (((long)(b * 16 + chunk) * 2) * 4096 + pix) * 8 + ilv(j);
    uint32_t* out = (uint32_t*)xt;
    out[base]         = pk2bf(h0, h1);
    out[base + 32768] = pk2bf(v0 - h0, v1 - h1);
}

// ---------------- weight prep: OIHW -> [ocg64][chunk16ic][hi/lo][tap][ocl][8 words] ----------------
__global__ void wprep_kernel(const float* __restrict__ W, float* __restrict__ dst,
                             int Cin, int Cout) {
    int idx = blockIdx.x * 256 + threadIdx.x;
    int cp = Cin >> 1;
    int total = Cout * cp * 9;
    if (idx >= total) return;
    int tap = idx % 9;
    int rem = idx / 9;
    int jp  = rem % cp;
    int oc  = rem / cp;
    float w0 = W[((long)oc * Cin + 2 * jp) * 9 + tap];
    float w1 = W[((long)oc * Cin + 2 * jp + 1) * 9 + tap];
    float h0 = bfhi(w0), h1 = bfhi(w1);
    int ocg = oc >> 6, ocl = oc & 63, chunk = jp >> 3, j = jp & 7;
    int nch = Cin >> 4;
    long base = (long)(ocg * nch + chunk) * 9216;
    uint32_t* d = (uint32_t*)dst;
    d[base +        (tap * 64 + ocl) * 8 + ilv(j)] = pk2bf(h0, h1);
    d[base + 4608 + (tap * 64 + ocl) * 8 + ilv(j)] = pk2bf(w0 - h0, w1 - h1);
}

// ======== bf16 3-term tensor-core 3x3 dilated conv, 2-stage cp.async pipeline ========
#define TSW   8448
#define SINW  16896
#define WW    9216
#define STAGEW 26112
#define CSM   ((2 * STAGEW + 1024) * 4)
template<bool AS>
__global__ void __launch_bounds__(512, 1) conv_mma_kernel(
    const float* __restrict__ in, const float* __restrict__ wtbase,
    float* __restrict__ outbase, int Cin,
    float* __restrict__ p1base, float* __restrict__ p2base)
{
    extern __shared__ float sm[];
    float* sRS = sm + 2 * STAGEW;
    float* sRQ = sRS + 512;

    const int ytile = blockIdx.x;
    const int b     = blockIdx.z;
    const int nchunk = Cin >> 4;
    int dil, ocg, Cout;
    const float* wt;
    float* out;
    float *p1, *p2;
    if (AS) {
        int br = blockIdx.y;
        dil = 3 * (br + 1); ocg = 0; Cout = 64;
        wt  = wtbase + (long)br * 147456;
        out = outbase + ((long)br * BATCH + b) * 64 * NPIX;
        p1  = p1base + br * 8192;
        p2  = p2base + br * 8192;
    } else {
        dil = 1; ocg = blockIdx.y; Cout = gridDim.y * 64;
        wt  = wtbase + (long)ocg * nchunk * WW;
        out = outbase + (long)b * Cout * NPIX;
        p1  = p1base; p2 = p2base;
    }
    in += (long)b * nchunk * 65536;

    const int t = threadIdx.x, lane = t & 31, w = t >> 5;
    const int g = lane >> 2, tq = lane & 3;
    const int mwarp = w >> 3;
    const int yr    = (w >> 1) & 3;
    const int nh    = w & 1;
    const int y0    = ytile * 4;

    const uint32_t smb = (uint32_t)__cvta_generic_to_shared(sm);

    for (int i = t; i < SINW; i += 512) { sm[i] = 0.f; sm[STAGEW + i] = 0.f; }
    __syncthreads();

    auto issue = [&](int c, int s) {
        const uint32_t stb = smb + (uint32_t)(s * STAGEW * 4);
        const float4* ws = (const float4*)(wt + (long)c * WW);
        const uint32_t swu = stb + (uint32_t)(SINW * 4);
        for (int i = t; i < 2304; i += 512)
            asm volatile("cp.async.cg.shared.global [%0], [%1], 16;\n"
                         :: "r"(swu + i * 16), "l"(ws + i));
#pragma unroll
        for (int e = t; e < 3072; e += 512) {
            int fx  = e & 127;
            int r   = e >> 7;
            int term = r / 12;
            int r2   = r - term * 12;
            int ky = r2 >> 2, yri = r2 & 3;
            int ry = y0 + yri + (ky - 1) * dil;
            int ok = (ry >= 0 && ry < 64);
            uint32_t dst = stb + (uint32_t)((term * TSW + (ky * 4 + yri) * 704 + 96) * 4 + fx * 16);
            const float4* src = (const float4*)(in + ((long)(c * 2 + term) * 4096 +
                                                      (ok ? ry : 0) * 64) * 8) + fx;
            int ssz = ok ? 16 : 0;
            asm volatile("cp.async.cg.shared.global [%0], [%1], 16, %2;\n"
                         :: "r"(dst), "l"(src), "r"(ssz));
        }
        asm volatile("cp.async.commit_group;\n");
    };

    float acc[2][4][4];
#pragma unroll
    for (int mf = 0; mf < 2; mf++)
#pragma unroll
        for (int nt = 0; nt < 4; nt++)
#pragma unroll
            for (int c = 0; c < 4; c++) acc[mf][nt][c] = 0.f;

    issue(0, 0);

    for (int chunk = 0; chunk < nchunk; chunk++) {
        const int s = chunk & 1;
        if (chunk + 1 < nchunk) {
            issue(chunk + 1, s ^ 1);
            asm volatile("cp.async.wait_group 1;\n" ::: "memory");
        } else {
            asm volatile("cp.async.wait_group 0;\n" ::: "memory");
        }
        __syncthreads();

        const uint32_t* sIn = (const uint32_t*)sm + s * STAGEW;
        const uint32_t* sW  = sIn + SINW;

#pragma unroll
        for (int tap = 0; tap < 9; tap++) {
            const int ky = tap / 3, kx = tap % 3;
            const uint32_t* wb = sW + (tap * 64 + mwarp * 32 + g) * 8 + 2 * tq;
            uint2 h0  = *(const uint2*)(wb);
            uint2 h0b = *(const uint2*)(wb + 64);
            uint2 h1  = *(const uint2*)(wb + 128);
            uint2 h1b = *(const uint2*)(wb + 192);
            uint2 l0  = *(const uint2*)(wb + 4608);
            uint2 l0b = *(const uint2*)(wb + 4672);
            uint2 l1  = *(const uint2*)(wb + 4736);
            uint2 l1b = *(const uint2*)(wb + 4800);
            uint32_t aH0[4] = {h0.x, h0b.x, h0.y, h0b.y};
            uint32_t aH1[4] = {h1.x, h1b.x, h1.y, h1b.y};
            uint32_t aL0[4] = {l0.x, l0b.x, l0.y, l0b.y};
            uint32_t aL1[4] = {l1.x, l1b.x, l1.y, l1b.y};
            const int rowoff = (ky * 4 + yr) * 704 +
                               (12 + nh * 32 + g + (kx - 1) * dil) * 8 + 2 * tq;
#pragma unroll
            for (int nt = 0; nt < 4; nt++) {
                uint2 bh = *(const uint2*)(sIn + rowoff + nt * 64);
                uint2 bl = *(const uint2*)(sIn + TSW + rowoff + nt * 64);
                mma16(acc[0][nt], aH0, bh.x, bh.y);
                mma16(acc[0][nt], aL0, bh.x, bh.y);
                mma16(acc[0][nt], aH0, bl.x, bl.y);
                mma16(acc[1][nt], aH1, bh.x, bh.y);
                mma16(acc[1][nt], aL1, bh.x, bh.y);
                mma16(acc[1][nt], aH1, bl.x, bl.y);
            }
        }
        __syncthreads();
    }

    // ---- epilogue: store + BN partials ----
    float s_[2][2] = {{0.f, 0.f}, {0.f, 0.f}};
    float q_[2][2] = {{0.f, 0.f}, {0.f, 0.f}};
    const int ocb = ocg * 64 + mwarp * 32;
#pragma unroll
    for (int mf = 0; mf < 2; mf++) {
        int oc = ocb + mf * 16 + g;
#pragma unroll
        for (int nt = 0; nt < 4; nt++) {
            int gx = (y0 + yr) * 64 + nh * 32 + nt * 8 + 2 * tq;
            float c0 = acc[mf][nt][0], c1 = acc[mf][nt][1];
            float c2 = acc[mf][nt][2], c3 = acc[mf][nt][3];
            out[(long)oc * NPIX + gx]           = c0;
            out[(long)oc * NPIX + gx + 1]       = c1;
            out[(long)(oc + 8) * NPIX + gx]     = c2;
            out[(long)(oc + 8) * NPIX + gx + 1] = c3;
            s_[mf][0] += c0 + c1; q_[mf][0] += c0 * c0 + c1 * c1;
            s_[mf][1] += c2 + c3; q_[mf][1] += c2 * c2 + c3 * c3;
        }
    }
#pragma unroll
    for (int mf = 0; mf < 2; mf++)
#pragma unroll
        for (int ro = 0; ro < 2; ro++) {
            float a = s_[mf][ro], qq = q_[mf][ro];
            a  += __shfl_xor_sync(0xffffffffu, a, 1);
            qq += __shfl_xor_sync(0xffffffffu, qq, 1);
            a  += __shfl_xor_sync(0xffffffffu, a, 2);
            qq += __shfl_xor_sync(0xffffffffu, qq, 2);
            if (tq == 0) {
                sRS[w * 32 + mf * 16 + ro * 8 + g] = a;
                sRQ[w * 32 + mf * 16 + ro * 8 + g] = qq;
            }
        }
    __syncthreads();
    if (t < 64) {
        int mw = t >> 5, cl = t & 31;
        float a = 0.f, qq = 0.f;
#pragma unroll
        for (int j = 0; j < 8; j++) {
            a  += sRS[(mw * 8 + j) * 32 + cl];
            qq += sRQ[(mw * 8 + j) * 32 + cl];
        }
        int slot = b * 16 + ytile;
        p1[slot * Cout + ocg * 64 + t] = a;
        p2[slot * Cout + ocg * 64 + t] = qq;
    }
}

// ---------------- BN finalize ----------------
__global__ void finalize_kernel(const float* __restrict__ p1, const float* __restrict__ p2,
                                const float* __restrict__ g, const float* __restrict__ be,
                                float* __restrict__ A, float* __restrict__ B,
                                int C, int nslots) {
    const int c = blockIdx.x, t = threadIdx.x;
    float s = 0.f, q = 0.f;
    for (int slot = t; slot < nslots; slot += 128) {
        s += p1[slot * C + c];
        q += p2[slot * C + c];
    }
    __shared__ float rs[4], rq[4];
#pragma unroll
    for (int off = 16; off; off >>= 1) {
        s += __shfl_down_sync(0xffffffffu, s, off);
        q += __shfl_down_sync(0xffffffffu, q, off);
    }
    int lane = t & 31, wp = t >> 5;
    if (!lane) { rs[wp] = s; rq[wp] = q; }
    __syncthreads();
    if (t == 0) {
        s = rs[0] + rs[1] + rs[2] + rs[3];
        q = rq[0] + rq[1] + rq[2] + rq[3];
        const float inv = 1.f / (float)(BATCH * NPIX);
        float mean = s * inv;
        float var  = q * inv - mean * mean;
        float a = g[c] * rsqrtf(var + 1e-5f);
        A[c] = a;
        B[c] = be[c] - mean * a;
    }
}

// ---------------- 1x1 conv Cout=64 with input-BN + stats (aspp1, exact fp32) ----------------
__global__ void __launch_bounds__(256) conv1x1_bn_kernel(
    const float* __restrict__ in, const float* __restrict__ w,
    float* __restrict__ out, int Cin,
    const float* __restrict__ Abn, const float* __restrict__ Bbn,
    float* __restrict__ p1, float* __restrict__ p2)
{
    const int p0 = blockIdx.x * 64;
    const int b  = blockIdx.z;
    in  += (long)b * Cin * NPIX;
    out += (long)b * 64  * NPIX;
    const int t = threadIdx.x, tx = t & 15, ty = t >> 4;

    __shared__ float sW [16 * 68];
    __shared__ float sIn[16 * 64];

    float acc[4][4];
#pragma unroll
    for (int r = 0; r < 4; r++)
#pragma unroll
        for (int c = 0; c < 4; c++) acc[r][c] = 0.f;

    for (int ic0 = 0; ic0 < Cin; ic0 += 16) {
        __syncthreads();
        for (int idx = t; idx < 1024; idx += 256) {
            int ic = idx & 15, oc = idx >> 4;
            sW[ic * 68 + oc] = w[(long)oc * Cin + ic0 + ic];
        }
        for (int idx = t; idx < 1024; idx += 256) {
            int ic = idx >> 6, px = idx & 63;
            int c = ic0 + ic;
            float v = in[c * NPIX + p0 + px];
            sIn[idx] = fmaxf(v * Abn[c] + Bbn[c], 0.f);
        }
        __syncthreads();
#pragma unroll
        for (int ic = 0; ic < 16; ic++) {
            float4 a  = *(const float4*)(sW  + ic * 68 + ty * 4);
            float4 xv = *(const float4*)(sIn + ic * 64 + tx * 4);
            float av[4] = {a.x, a.y, a.z, a.w};
            float xa[4] = {xv.x, xv.y, xv.z, xv.w};
#pragma unroll
            for (int r = 0; r < 4; r++)
#pragma unroll
                for (int c = 0; c < 4; c++) acc[r][c] += av[r] * xa[c];
        }
    }
    float sums[4], sqs[4];
#pragma unroll
    for (int r = 0; r < 4; r++) {
        float s = 0.f, q = 0.f;
        float* op = out + (long)(ty * 4 + r) * NPIX + p0 + tx * 4;
#pragma unroll
        for (int c = 0; c < 4; c++) {
            float v = acc[r][c];
            op[c] = v; s += v; q += v * v;
        }
        sums[r] = s; sqs[r] = q;
    }
#pragma unroll
    for (int r = 0; r < 4; r++) {
        float a = sums[r], q = sqs[r];
#pragma unroll
        for (int off = 1; off < 16; off <<= 1) {
            a += __shfl_xor_sync(0xffffffffu, a, off);
            q += __shfl_xor_sync(0xffffffffu, q, off);
        }
        if (tx == 0) {
            int c = ty * 4 + r;
            int slot = b * 64 + blockIdx.x;
            p1[slot * 64 + c] = a;
            p2[slot * 64 + c] = q;
        }
    }
}

// ---------------- fused q/k/v 1x1 projections -> q plain + fp16 K'/V fragment words ----------------
__global__ void __launch_bounds__(256) qkv_kernel(
    const float* __restrict__ brin,
    const float* __restrict__ wq, const float* __restrict__ bq,
    const float* __restrict__ wk, const float* __restrict__ bk,
    const float* __restrict__ wv, const float* __restrict__ bv,
    float* __restrict__ qo, float* __restrict__ kf, float* __restrict__ vf,
    const float* __restrict__ Abase, const float* __restrict__ Bbase)
{
    const int p0  = blockIdx.x * 64;
    const int img = blockIdx.z;
    const int br  = img >> 2;
    const long ib = (long)img * 64 * NPIX;
    const float* A  = Abase + (2 + br) * 256;
    const float* Bb = Bbase + (2 + br) * 256;
    const int t = threadIdx.x, tx = t & 15, ty = t >> 4;

    uint32_t* kfw = (uint32_t*)(kf + (long)img * 262144);  // [j][64 words]
    uint32_t* vfw = (uint32_t*)(vf + (long)img * 131072);  // [d][jg 256][8 words]

    __shared__ float sW [3 * 16 * 64];
    __shared__ float sIn[16 * 64];

    float acc[3][4][4];
#pragma unroll
    for (int m = 0; m < 3; m++)
#pragma unroll
        for (int r = 0; r < 4; r++)
#pragma unroll
            for (int c = 0; c < 4; c++) acc[m][r][c] = 0.f;

    for (int ic0 = 0; ic0 < 64; ic0 += 16) {
        __syncthreads();
        for (int i = t; i < 1024; i += 256) {
            int ic = i >> 6, px = i & 63;
            int c = ic0 + ic;
            float v = brin[ib + (long)c * NPIX + p0 + px];
            sIn[i] = fmaxf(v * A[c] + Bb[c], 0.f);
        }
        for (int i = t; i < 3072; i += 256) {
            int m = i >> 10, r = i & 1023;
            int ic = r & 15, oc = r >> 4;
            const float* wm = (m == 0) ? wq : ((m == 1) ? wk : wv);
            sW[m * 1024 + ic * 64 + oc] = wm[oc * 64 + ic0 + ic];
        }
        __syncthreads();
#pragma unroll
        for (int ic = 0; ic < 16; ic++) {
            float4 xv = *(const float4*)(sIn + ic * 64 + tx * 4);
            float xa[4] = {xv.x, xv.y, xv.z, xv.w};
#pragma unroll
            for (int m = 0; m < 3; m++) {
                float4 a = *(const float4*)(sW + m * 1024 + ic * 64 + ty * 4);
                float av[4] = {a.x, a.y, a.z, a.w};
#pragma unroll
                for (int r = 0; r < 4; r++)
#pragma unroll
                    for (int c = 0; c < 4; c++) acc[m][r][c] += av[r] * xa[c];
            }
        }
    }
    // ---- epilogue: add bias, emit plain q + packed fp16 fragments ----
    float val[3][4][4];
    const float* bs[3] = {bq, bk, bv};
#pragma unroll
    for (int m = 0; m < 3; m++)
#pragma unroll
        for (int r = 0; r < 4; r++) {
            float bb = bs[m][ty * 4 + r];
#pragma unroll
            for (int ci = 0; ci < 4; ci++) val[m][r][ci] = acc[m][r][ci] + bb;
        }
    // plain q
#pragma unroll
    for (int r = 0; r < 4; r++)
#pragma unroll
        for (int ci = 0; ci < 4; ci++)
            qo[ib + (long)(ty * 4 + r) * NPIX + p0 + tx * 4 + ci] = val[0][r][ci];
    // K' words: kk = oc (from k) and 64+oc (from q); pack consecutive-oc pairs
#pragma unroll
    for (int m = 0; m < 2; m++) {
#pragma unroll
        for (int rp = 0; rp < 4; rp += 2) {
            int kk0 = (m == 0 ? 64 : 0) + ty * 4 + rp;   // even
            int grp = kk0 >> 4, j2 = (kk0 & 15) >> 1;
            int woff = grp * 8 + ilv(j2);
#pragma unroll
            for (int ci = 0; ci < 4; ci++) {
                int j = p0 + tx * 4 + ci;
                kfw[j * 64 + woff] = pk2h(val[m][rp][ci], val[m][rp + 1][ci]);
            }
        }
    }
    // V words: pack consecutive-j pairs
#pragma unroll
    for (int r = 0; r < 4; r++) {
        int d = ty * 4 + r;
#pragma unroll
        for (int ci = 0; ci < 4; ci += 2) {
            int j = p0 + tx * 4 + ci;                    // even
            int jg = j >> 4, j2 = (j & 15) >> 1;
            vfw[(d * 256 + jg) * 8 + ilv(j2)] = pk2h(val[2][r][ci], val[2][r][ci + 1]);
        }
    }
}

// ---------------- pos table ----------------
__global__ void pos_kernel(const float* __restrict__ rh, const float* __restrict__ rw) {
    int idx = blockIdx.x * blockDim.x + threadIdx.x;
    if (idx >= 64 * NPIX) return;
    int d = idx >> 12, n = idx & 4095, a = n >> 6, bb = n & 63;
    g_pos[idx] = rh[d * 64 + bb] + rw[d * 64 + a];
}

// ================= fp16 k16 fragment-direct flash attention (zero smem) =================
#define LOG2E 1.44269504088896f

__global__ void __launch_bounds__(256, 1) flash_mma_kernel(
    const float* __restrict__ qg, const float* __restrict__ kf,
    const float* __restrict__ vf, float* __restrict__ outg)
{
    const int i0 = blockIdx.x * 128;
    const int b  = blockIdx.y, br = blockIdx.z;
    const int img = br * BATCH + b;
    const float* q = qg + (long)img * 64 * NPIX;
    const uint2* KF2 = (const uint2*)(kf + (long)img * 262144);
    const uint2* VF2 = (const uint2*)(vf + (long)img * 131072);
    float* outp = outg + (long)(b * 256 + br * 64) * NPIX;

    const int t = threadIdx.x;
    const int lane = t & 31, w = t >> 5;
    const int g = lane >> 2, tq = lane & 3;

    // Q' fp16 A-fragments (log2e pre-scaled), 8 k16-groups
    uint32_t Qf[8][4];
    {
        int i_r = i0 + w * 16 + g;
#pragma unroll
        for (int kp = 0; kp < 8; kp++) {
            int kc = kp * 16 + 2 * tq;
            const float* pa = (kc     < 64) ? (q + kc * NPIX)       : (g_pos + (kc - 64) * NPIX);
            const float* pb = (kc + 1 < 64) ? (q + (kc + 1) * NPIX) : (g_pos + (kc - 63) * NPIX);
            const float* pc = (kc + 8 < 64) ? (q + (kc + 8) * NPIX) : (g_pos + (kc - 56) * NPIX);
            const float* pd = (kc + 9 < 64) ? (q + (kc + 9) * NPIX) : (g_pos + (kc - 55) * NPIX);
            Qf[kp][0] = pk2h(pa[i_r] * LOG2E,     pb[i_r] * LOG2E);
            Qf[kp][1] = pk2h(pa[i_r + 8] * LOG2E, pb[i_r + 8] * LOG2E);
            Qf[kp][2] = pk2h(pc[i_r] * LOG2E,     pd[i_r] * LOG2E);
            Qf[kp][3] = pk2h(pc[i_r + 8] * LOG2E, pd[i_r + 8] * LOG2E);
        }
    }

    float Oa[8][4];
#pragma unroll
    for (int nt = 0; nt < 8; nt++)
#pragma unroll
        for (int c = 0; c < 4; c++) Oa[nt][c] = 0.f;
    float m0 = -CUDART_INF_F, m1 = -CUDART_INF_F, l0 = 0.f, l1 = 0.f;

    for (int j0 = 0; j0 < NPIX; j0 += 64) {
        // ---- S = Q' K' (fp16 k16 fragments direct from gmem) ----
        float Sa[8][4];
#pragma unroll
        for (int nt = 0; nt < 8; nt++)
#pragma unroll
            for (int c = 0; c < 4; c++) Sa[nt][c] = 0.f;
#pragma unroll
        for (int kp = 0; kp < 8; kp++) {
#pragma unroll
            for (int nt = 0; nt < 8; nt++) {
                uint2 kb = KF2[(j0 + nt * 8 + g) * 32 + kp * 4 + tq];
                mma16h(Sa[nt], Qf[kp], kb.x, kb.y);
            }
        }

        // ---- online softmax (log2 domain) ----
        float mx0 = -CUDART_INF_F, mx1 = -CUDART_INF_F;
#pragma unroll
        for (int nt = 0; nt < 8; nt++) {
            mx0 = fmaxf(mx0, fmaxf(Sa[nt][0], Sa[nt][1]));
            mx1 = fmaxf(mx1, fmaxf(Sa[nt][2], Sa[nt][3]));
        }
        mx0 = fmaxf(mx0, __shfl_xor_sync(0xffffffffu, mx0, 1));
        mx0 = fmaxf(mx0, __shfl_xor_sync(0xffffffffu, mx0, 2));
        mx1 = fmaxf(mx1, __shfl_xor_sync(0xffffffffu, mx1, 1));
        mx1 = fmaxf(mx1, __shfl_xor_sync(0xffffffffu, mx1, 2));
        float mn0 = fmaxf(m0, mx0), mn1 = fmaxf(m1, mx1);
        float al0 = ex2f(m0 - mn0), al1 = ex2f(m1 - mn1);

        float su0 = 0.f, su1 = 0.f;
#pragma unroll
        for (int nt = 0; nt < 8; nt++) {
            Sa[nt][0] = ex2f(Sa[nt][0] - mn0);
            Sa[nt][1] = ex2f(Sa[nt][1] - mn0);
            Sa[nt][2] = ex2f(Sa[nt][2] - mn1);
            Sa[nt][3] = ex2f(Sa[nt][3] - mn1);
            su0 += Sa[nt][0] + Sa[nt][1];
            su1 += Sa[nt][2] + Sa[nt][3];
        }
        su0 += __shfl_xor_sync(0xffffffffu, su0, 1);
        su0 += __shfl_xor_sync(0xffffffffu, su0, 2);
        su1 += __shfl_xor_sync(0xffffffffu, su1, 1);
        su1 += __shfl_xor_sync(0xffffffffu, su1, 2);
        l0 = l0 * al0 + su0; l1 = l1 * al1 + su1;
        m0 = mn0; m1 = mn1;
#pragma unroll
        for (int nt = 0; nt < 8; nt++) {
            Oa[nt][0] *= al0; Oa[nt][1] *= al0;
            Oa[nt][2] *= al1; Oa[nt][3] *= al1;
        }

        // ---- O += P V : P A-fragments built in registers (no smem round-trip) ----
#pragma unroll
        for (int gr = 0; gr < 4; gr++) {
            uint32_t a[4] = {
                pk2h(Sa[2 * gr][0],     Sa[2 * gr][1]),
                pk2h(Sa[2 * gr][2],     Sa[2 * gr][3]),
                pk2h(Sa[2 * gr + 1][0], Sa[2 * gr + 1][1]),
                pk2h(Sa[2 * gr + 1][2], Sa[2 * gr + 1][3])
            };
#pragma unroll
            for (int nt = 0; nt < 8; nt++) {
                uint2 vb = VF2[((nt * 8 + g) * 256 + (j0 >> 4) + gr) * 4 + tq];
                mma16h(Oa[nt], a, vb.x, vb.y);
            }
        }
    }

    float inv0 = 1.f / l0, inv1 = 1.f / l1;
    int pix = i0 + w * 16 + g;
#pragma unroll
    for (int nt = 0; nt < 8; nt++) {
        int d0 = nt * 8 + 2 * tq;
        outp[(long)d0 * NPIX + pix]           = Oa[nt][0] * inv0;
        outp[(long)(d0 + 1) * NPIX + pix]     = Oa[nt][1] * inv0;
        outp[(long)d0 * NPIX + pix + 8]       = Oa[nt][2] * inv1;
        outp[(long)(d0 + 1) * NPIX + pix + 8] = Oa[nt][3] * inv1;
    }
}

// ---------------- host orchestration ----------------
extern "C" void kernel_launch(void* const* d_in, const int* in_sizes, int n_in,
                              void* d_out, int out_size) {
    const float* x      = (const float*)d_in[0];
    const float* dc_w1  = (const float*)d_in[1];
    const float* dc_g1  = (const float*)d_in[3];
    const float* dc_be1 = (const float*)d_in[4];
    const float* dc_w2  = (const float*)d_in[5];
    const float* dc_g2  = (const float*)d_in[7];
    const float* dc_be2 = (const float*)d_in[8];
    const float* aw[4]  = {(const float*)d_in[9],  (const float*)d_in[12],
                           (const float*)d_in[15], (const float*)d_in[18]};
    const float* ag[4]  = {(const float*)d_in[10], (const float*)d_in[13],
                           (const float*)d_in[16], (const float*)d_in[19]};
    const float* ab[4]  = {(const float*)d_in[11], (const float*)d_in[14],
                           (const float*)d_in[17], (const float*)d_in[20]};
    const float* wq = (const float*)d_in[21]; const float* bq = (const float*)d_in[22];
    const float* wk = (const float*)d_in[23]; const float* bk = (const float*)d_in[24];
    const float* wv = (const float*)d_in[25]; const float* bv = (const float*)d_in[26];
    const float* rel_h = (const float*)d_in[27];
    const float* rel_w = (const float*)d_in[28];

    float *buf1, *buf2, *xt0, *xt1, *xt2, *brb, *qb, *kfb, *vfb;
    float *p1, *p2, *An, *Bn, *wt;
    cudaGetSymbolAddress((void**)&buf1, g_buf1);
    cudaGetSymbolAddress((void**)&buf2, g_buf2);
    cudaGetSymbolAddress((void**)&xt0,  g_xt0);
    cudaGetSymbolAddress((void**)&xt1,  g_xt1);
    cudaGetSymbolAddress((void**)&xt2,  g_xt2);
    cudaGetSymbolAddress((void**)&brb,  g_br);
    cudaGetSymbolAddress((void**)&qb,   g_q);
    cudaGetSymbolAddress((void**)&kfb,  g_kf);
    cudaGetSymbolAddress((void**)&vfb,  g_vf);
    cudaGetSymbolAddress((void**)&p1,   g_p1);
    cudaGetSymbolAddress((void**)&p2,   g_p2);
    cudaGetSymbolAddress((void**)&An,   g_An);
    cudaGetSymbolAddress((void**)&Bn,   g_Bn);
    cudaGetSymbolAddress((void**)&wt,   g_wt);

    float* wt1 = wt;                  // conv1: 294912
    float* wt2 = wt + 294912;         // conv2: 589824
    float* wtA = wt + 884736;         // aspp:  3 x 147456

    cudaFuncSetAttribute((const void*)conv_mma_kernel<false>,
                         cudaFuncAttributeMaxDynamicSharedMemorySize, CSM);
    cudaFuncSetAttribute((const void*)conv_mma_kernel<true>,
                         cudaFuncAttributeMaxDynamicSharedMemorySize, CSM);

    // weight prep (bf16 hi/lo, fragment-packed)
    wprep_kernel<<<(256 * 64 * 9 + 255) / 256, 256>>>(dc_w1, wt1, 128, 256);
    wprep_kernel<<<(256 * 128 * 9 + 255) / 256, 256>>>(dc_w2, wt2, 256, 256);
    for (int i = 0; i < 3; i++)
        wprep_kernel<<<(64 * 128 * 9 + 255) / 256, 256>>>(
            aw[i + 1], wtA + (long)i * 147456, 256, 64);

    // mpconv
    maxpool_xt_kernel<<<(BATCH * 64 * NPIX + 255) / 256, 256>>>(x, xt0);
    conv_mma_kernel<false><<<dim3(16, 4, BATCH), 512, CSM>>>(
        xt0, wt1, buf1, 128, p1, p2);
    finalize_kernel<<<256, 128>>>(p1, p2, dc_g1, dc_be1, An + 0, Bn + 0, 256, 64);
    bnprep_xt_kernel<<<(BATCH * 128 * NPIX + 255) / 256, 256>>>(buf1, xt1, An + 0, Bn + 0);
    conv_mma_kernel<false><<<dim3(16, 4, BATCH), 512, CSM>>>(
        xt1, wt2, buf2, 256, p1, p2);
    finalize_kernel<<<256, 128>>>(p1, p2, dc_g2, dc_be2, An + 256, Bn + 256, 256, 64);
    bnprep_xt_kernel<<<(BATCH * 128 * NPIX + 255) / 256, 256>>>(buf2, xt2, An + 256, Bn + 256);

    // ASPP dilated branches fused; 1x1 branch exact
    conv_mma_kernel<true><<<dim3(16, 3, BATCH), 512, CSM>>>(
        xt2, wtA, brb + (long)BATCH * 64 * NPIX, 256, p1, p2);
    for (int i = 0; i < 3; i++)
        finalize_kernel<<<64, 128>>>(p1 + i * 8192, p2 + i * 8192, ag[i + 1], ab[i + 1],
                                     An + (3 + i) * 256, Bn + (3 + i) * 256, 64, 64);
    conv1x1_bn_kernel<<<dim3(64, 1, BATCH), 256>>>(
        buf2, aw[0], brb, 256, An + 256, Bn + 256, p1 + 32768, p2 + 32768);
    finalize_kernel<<<64, 128>>>(p1 + 32768, p2 + 32768, ag[0], ab[0],
                                 An + 2 * 256, Bn + 2 * 256, 64, 256);

    // fused qkv (fp16 fragment emission) + pos
    qkv_kernel<<<dim3(64, 1, 16), 256>>>(brb, wq, bq, wk, bk, wv, bv,
                                         qb, kfb, vfb, An, Bn);
    pos_kernel<<<(64 * NPIX + 255) / 256, 256>>>(rel_h, rel_w);

    // fp16 flash attention (no smem) -> concat output
    flash_mma_kernel<<<dim3(32, BATCH, 4), 256>>>(qb, kfb, vfb, (float*)d_out);
}

// round 15
// speedup vs baseline: 1.6977x; 1.1236x over previous
#include <cuda_runtime.h>
#include <cuda_fp16.h>
#include <math_constants.h>
#include <stdint.h>

#define BATCH 4
#define NPIX 4096   // 64*64

// ---------------- scratch (device globals; no cudaMalloc allowed) ----------------
__device__ float g_buf1 [BATCH * 256 * NPIX];      // conv1 raw out (fp32)
__device__ float g_buf2 [BATCH * 256 * NPIX];      // conv2 raw out (fp32)
__device__ float g_xt0  [BATCH * 8  * NPIX * 8];   // conv1 input packed fp16 (single plane)
__device__ float g_xt1  [BATCH * 16 * NPIX * 8];   // conv2 input packed
__device__ float g_xt2  [BATCH * 16 * NPIX * 8];   // aspp  input packed
__device__ float g_br  [4 * BATCH * 64 * NPIX];
__device__ float g_q   [4 * BATCH * 64 * NPIX];    // plain q
__device__ float g_kf  [16 * 4096 * 64];           // K' packed fp16 words
__device__ float g_vf  [16 * 64 * 256 * 8];        // V  packed fp16 words
__device__ float g_pos [64 * NPIX];
__device__ float g_p1  [256 * 256];
__device__ float g_p2  [256 * 256];
__device__ float g_An  [6 * 256];
__device__ float g_Bn  [6 * 256];
__device__ float g_wt  [1327104];   // packed fp16 hi/lo conv weights

__device__ __forceinline__ float ex2f(float x) {
    float y;
    asm("ex2.approx.ftz.f32 %0, %1;" : "=f"(y) : "f"(x));
    return y;
}
__device__ __forceinline__ void mma16h(float d[4], const uint32_t a[4],
                                       uint32_t b0, uint32_t b1) {
    asm volatile(
        "mma.sync.aligned.m16n8k16.row.col.f32.f16.f16.f32 "
        "{%0,%1,%2,%3},{%4,%5,%6,%7},{%8,%9},{%0,%1,%2,%3};"
        : "+f"(d[0]), "+f"(d[1]), "+f"(d[2]), "+f"(d[3])
        : "r"(a[0]), "r"(a[1]), "r"(a[2]), "r"(a[3]), "r"(b0), "r"(b1));
}
__device__ __forceinline__ int ilv(int klo) { return (klo & 3) * 2 + (klo >> 2); }
__device__ __forceinline__ uint32_t pk2h(float a, float b) {
    __half2 t = __floats2half2_rn(a, b);
    return *reinterpret_cast<uint32_t*>(&t);
}
__device__ __forceinline__ float hfhi(float x) {
    return __half2float(__float2half(x));
}

// ---------------- maxpool 2x2 -> packed fp16 channel-pair layout ----------------
// xt layout: [b][chunk Cin/16][pix 4096][8 words], word slot ilv(j) = channels (2j,2j+1)
__global__ void maxpool_xt_kernel(const float* __restrict__ x, float* __restrict__ xt) {
    int idx = blockIdx.x * blockDim.x + threadIdx.x;
    if (idx >= BATCH * 64 * NPIX) return;
    int pix = idx & 4095, rest = idx >> 12;
    int cp = rest & 63, b = rest >> 6;
    int y = pix >> 6, xx = pix & 63;
    float v[2];
#pragma unroll
    for (int e = 0; e < 2; e++) {
        const float* src = x + ((long)(b * 128 + 2 * cp + e) * 128 + 2 * y) * 128 + 2 * xx;
        v[e] = fmaxf(fmaxf(src[0], src[1]), fmaxf(src[128], src[129]));
    }
    int chunk = cp >> 3, j = cp & 7;
    long base = (((long)(b * 8 + chunk)) * 4096 + pix) * 8 + ilv(j);
    ((uint32_t*)xt)[base] = pk2h(v[0], v[1]);
}

// ---------------- bnprep: raw fp32 [c][pix] -> relu(BN) -> packed fp16 ----------------
__global__ void bnprep_xt_kernel(const float* __restrict__ in, float* __restrict__ xt,
                                 const float* __restrict__ A, const float* __restrict__ B) {
    int idx = blockIdx.x * blockDim.x + threadIdx.x;
    if (idx >= BATCH * 128 * NPIX) return;
    int pix = idx & 4095, rest = idx >> 12;
    int cp = rest & 127, b = rest >> 7;
    int c0 = 2 * cp;
    float v0 = fmaxf(in[((long)(b * 256 + c0)) * NPIX + pix] * A[c0] + B[c0], 0.f);
    float v1 = fmaxf(in[((long)(b * 256 + c0 + 1)) * NPIX + pix] * A[c0 + 1] + B[c0 + 1], 0.f);
    int chunk = cp >> 3, j = cp & 7;
    long base = (((long)(b * 16 + chunk)) * 4096 + pix) * 8 + ilv(j);
    ((uint32_t*)xt)[base] = pk2h(v0, v1);
}

// ---------------- weight prep: OIHW -> [ocg64][chunk16ic][hi/lo][tap][ocl][8 words] ----------------
__global__ void wprep_kernel(const float* __restrict__ W, float* __restrict__ dst,
                             int Cin, int Cout) {
    int idx = blockIdx.x * 256 + threadIdx.x;
    int cp = Cin >> 1;
    int total = Cout * cp * 9;
    if (idx >= total) return;
    int tap = idx % 9;
    int rem = idx / 9;
    int jp  = rem % cp;
    int oc  = rem / cp;
    float w0 = W[((long)oc * Cin + 2 * jp) * 9 + tap];
    float w1 = W[((long)oc * Cin + 2 * jp + 1) * 9 + tap];
    float h0 = hfhi(w0), h1 = hfhi(w1);
    int ocg = oc >> 6, ocl = oc & 63, chunk = jp >> 3, j = jp & 7;
    int nch = Cin >> 4;
    long base = (long)(ocg * nch + chunk) * 9216;
    uint32_t* d = (uint32_t*)dst;
    d[base +        (tap * 64 + ocl) * 8 + ilv(j)] = pk2h(h0, h1);
    d[base + 4608 + (tap * 64 + ocl) * 8 + ilv(j)] = pk2h(w0 - h0, w1 - h1);
}

// ======== fp16 2-term tensor-core 3x3 dilated conv, 2-stage cp.async pipeline ========
// 512 thr = 16 warps (mwarp 2 x yr 4 x nh 2). CTA tile: 64 oc x 256 px (4 y rows).
// warp m32 x n32. K-chunk = 16 ic (k16). terms: (Wh + Wl) * X, X single fp16.
#define SINW  8448          // input words ([12 rows][88px][8w])
#define WW    9216          // weight words per chunk (hi+lo)
#define STAGEW 17664
#define CSM   ((2 * STAGEW + 1024) * 4)
template<bool AS>
__global__ void __launch_bounds__(512, 1) conv_mma_kernel(
    const float* __restrict__ in, const float* __restrict__ wtbase,
    float* __restrict__ outbase, int Cin,
    float* __restrict__ p1base, float* __restrict__ p2base)
{
    extern __shared__ float sm[];
    float* sRS = sm + 2 * STAGEW;
    float* sRQ = sRS + 512;

    const int ytile = blockIdx.x;
    const int b     = blockIdx.z;
    const int nchunk = Cin >> 4;
    int dil, ocg, Cout;
    const float* wt;
    float* out;
    float *p1, *p2;
    if (AS) {
        int br = blockIdx.y;
        dil = 3 * (br + 1); ocg = 0; Cout = 64;
        wt  = wtbase + (long)br * 147456;
        out = outbase + ((long)br * BATCH + b) * 64 * NPIX;
        p1  = p1base + br * 8192;
        p2  = p2base + br * 8192;
    } else {
        dil = 1; ocg = blockIdx.y; Cout = gridDim.y * 64;
        wt  = wtbase + (long)ocg * nchunk * WW;
        out = outbase + (long)b * Cout * NPIX;
        p1  = p1base; p2 = p2base;
    }
    in += (long)b * nchunk * 32768;       // [chunk][4096 pix][8 words]

    const int t = threadIdx.x, lane = t & 31, w = t >> 5;
    const int g = lane >> 2, tq = lane & 3;
    const int mwarp = w >> 3;
    const int yr    = (w >> 1) & 3;
    const int nh    = w & 1;
    const int y0    = ytile * 4;

    const uint32_t smb = (uint32_t)__cvta_generic_to_shared(sm);

    for (int i = t; i < SINW; i += 512) { sm[i] = 0.f; sm[STAGEW + i] = 0.f; }
    __syncthreads();

    auto issue = [&](int c, int s) {
        const uint32_t stb = smb + (uint32_t)(s * STAGEW * 4);
        const float4* ws = (const float4*)(wt + (long)c * WW);
        const uint32_t swu = stb + (uint32_t)(SINW * 4);
        for (int i = t; i < 2304; i += 512)
            asm volatile("cp.async.cg.shared.global [%0], [%1], 16;\n"
                         :: "r"(swu + i * 16), "l"(ws + i));
        // inputs: 12 rows x 128 float4, OOB rows zero-filled
#pragma unroll
        for (int e = t; e < 1536; e += 512) {
            int fx  = e & 127;
            int r   = e >> 7;              // 0..11
            int ky = r >> 2, yri = r & 3;
            int ry = y0 + yri + (ky - 1) * dil;
            int ok = (ry >= 0 && ry < 64);
            uint32_t dst = stb + (uint32_t)(((ky * 4 + yri) * 704 + 96) * 4 + fx * 16);
            const float4* src = (const float4*)(in + ((long)c * 4096 +
                                                      (ok ? ry : 0) * 64) * 8) + fx;
            int ssz = ok ? 16 : 0;
            asm volatile("cp.async.cg.shared.global [%0], [%1], 16, %2;\n"
                         :: "r"(dst), "l"(src), "r"(ssz));
        }
        asm volatile("cp.async.commit_group;\n");
    };

    float acc[2][4][4];
#pragma unroll
    for (int mf = 0; mf < 2; mf++)
#pragma unroll
        for (int nt = 0; nt < 4; nt++)
#pragma unroll
            for (int c = 0; c < 4; c++) acc[mf][nt][c] = 0.f;

    issue(0, 0);

    for (int chunk = 0; chunk < nchunk; chunk++) {
        const int s = chunk & 1;
        if (chunk + 1 < nchunk) {
            issue(chunk + 1, s ^ 1);
            asm volatile("cp.async.wait_group 1;\n" ::: "memory");
        } else {
            asm volatile("cp.async.wait_group 0;\n" ::: "memory");
        }
        __syncthreads();

        const uint32_t* sIn = (const uint32_t*)sm + s * STAGEW;
        const uint32_t* sW  = sIn + SINW;

#pragma unroll
        for (int tap = 0; tap < 9; tap++) {
            const int ky = tap / 3, kx = tap % 3;
            const uint32_t* wb = sW + (tap * 64 + mwarp * 32 + g) * 8 + 2 * tq;
            uint2 h0  = *(const uint2*)(wb);
            uint2 h0b = *(const uint2*)(wb + 64);
            uint2 h1  = *(const uint2*)(wb + 128);
            uint2 h1b = *(const uint2*)(wb + 192);
            uint2 l0  = *(const uint2*)(wb + 4608);
            uint2 l0b = *(const uint2*)(wb + 4672);
            uint2 l1  = *(const uint2*)(wb + 4736);
            uint2 l1b = *(const uint2*)(wb + 4800);
            uint32_t aH0[4] = {h0.x, h0b.x, h0.y, h0b.y};
            uint32_t aH1[4] = {h1.x, h1b.x, h1.y, h1b.y};
            uint32_t aL0[4] = {l0.x, l0b.x, l0.y, l0b.y};
            uint32_t aL1[4] = {l1.x, l1b.x, l1.y, l1b.y};
            const int rowoff = (ky * 4 + yr) * 704 +
                               (12 + nh * 32 + g + (kx - 1) * dil) * 8 + 2 * tq;
#pragma unroll
            for (int nt = 0; nt < 4; nt++) {
                uint2 bh = *(const uint2*)(sIn + rowoff + nt * 64);
                mma16h(acc[0][nt], aH0, bh.x, bh.y);
                mma16h(acc[0][nt], aL0, bh.x, bh.y);
                mma16h(acc[1][nt], aH1, bh.x, bh.y);
                mma16h(acc[1][nt], aL1, bh.x, bh.y);
            }
        }
        __syncthreads();
    }

    // ---- epilogue: store + BN partials ----
    float s_[2][2] = {{0.f, 0.f}, {0.f, 0.f}};
    float q_[2][2] = {{0.f, 0.f}, {0.f, 0.f}};
    const int ocb = ocg * 64 + mwarp * 32;
#pragma unroll
    for (int mf = 0; mf < 2; mf++) {
        int oc = ocb + mf * 16 + g;
#pragma unroll
        for (int nt = 0; nt < 4; nt++) {
            int gx = (y0 + yr) * 64 + nh * 32 + nt * 8 + 2 * tq;
            float c0 = acc[mf][nt][0], c1 = acc[mf][nt][1];
            float c2 = acc[mf][nt][2], c3 = acc[mf][nt][3];
            out[(long)oc * NPIX + gx]           = c0;
            out[(long)oc * NPIX + gx + 1]       = c1;
            out[(long)(oc + 8) * NPIX + gx]     = c2;
            out[(long)(oc + 8) * NPIX + gx + 1] = c3;
            s_[mf][0] += c0 + c1; q_[mf][0] += c0 * c0 + c1 * c1;
            s_[mf][1] += c2 + c3; q_[mf][1] += c2 * c2 + c3 * c3;
        }
    }
#pragma unroll
    for (int mf = 0; mf < 2; mf++)
#pragma unroll
        for (int ro = 0; ro < 2; ro++) {
            float a = s_[mf][ro], qq = q_[mf][ro];
            a  += __shfl_xor_sync(0xffffffffu, a, 1);
            qq += __shfl_xor_sync(0xffffffffu, qq, 1);
            a  += __shfl_xor_sync(0xffffffffu, a, 2);
            qq += __shfl_xor_sync(0xffffffffu, qq, 2);
            if (tq == 0) {
                sRS[w * 32 + mf * 16 + ro * 8 + g] = a;
                sRQ[w * 32 + mf * 16 + ro * 8 + g] = qq;
            }
        }
    __syncthreads();
    if (t < 64) {
        int mw = t >> 5, cl = t & 31;
        float a = 0.f, qq = 0.f;
#pragma unroll
        for (int j = 0; j < 8; j++) {
            a  += sRS[(mw * 8 + j) * 32 + cl];
            qq += sRQ[(mw * 8 + j) * 32 + cl];
        }
        int slot = b * 16 + ytile;
        p1[slot * Cout + ocg * 64 + t] = a;
        p2[slot * Cout + ocg * 64 + t] = qq;
    }
}

// ---------------- BN finalize ----------------
__global__ void finalize_kernel(const float* __restrict__ p1, const float* __restrict__ p2,
                                const float* __restrict__ g, const float* __restrict__ be,
                                float* __restrict__ A, float* __restrict__ B,
                                int C, int nslots) {
    const int c = blockIdx.x, t = threadIdx.x;
    float s = 0.f, q = 0.f;
    for (int slot = t; slot < nslots; slot += 128) {
        s += p1[slot * C + c];
        q += p2[slot * C + c];
    }
    __shared__ float rs[4], rq[4];
#pragma unroll
    for (int off = 16; off; off >>= 1) {
        s += __shfl_down_sync(0xffffffffu, s, off);
        q += __shfl_down_sync(0xffffffffu, q, off);
    }
    int lane = t & 31, wp = t >> 5;
    if (!lane) { rs[wp] = s; rq[wp] = q; }
    __syncthreads();
    if (t == 0) {
        s = rs[0] + rs[1] + rs[2] + rs[3];
        q = rq[0] + rq[1] + rq[2] + rq[3];
        const float inv = 1.f / (float)(BATCH * NPIX);
        float mean = s * inv;
        float var  = q * inv - mean * mean;
        float a = g[c] * rsqrtf(var + 1e-5f);
        A[c] = a;
        B[c] = be[c] - mean * a;
    }
}

// ---------------- 1x1 conv Cout=64 with input-BN + stats (aspp1, exact fp32) ----------------
__global__ void __launch_bounds__(256) conv1x1_bn_kernel(
    const float* __restrict__ in, const float* __restrict__ w,
    float* __restrict__ out, int Cin,
    const float* __restrict__ Abn, const float* __restrict__ Bbn,
    float* __restrict__ p1, float* __restrict__ p2)
{
    const int p0 = blockIdx.x * 64;
    const int b  = blockIdx.z;
    in  += (long)b * Cin * NPIX;
    out += (long)b * 64  * NPIX;
    const int t = threadIdx.x, tx = t & 15, ty = t >> 4;

    __shared__ float sW [16 * 68];
    __shared__ float sIn[16 * 64];

    float acc[4][4];
#pragma unroll
    for (int r = 0; r < 4; r++)
#pragma unroll
        for (int c = 0; c < 4; c++) acc[r][c] = 0.f;

    for (int ic0 = 0; ic0 < Cin; ic0 += 16) {
        __syncthreads();
        for (int idx = t; idx < 1024; idx += 256) {
            int ic = idx & 15, oc = idx >> 4;
            sW[ic * 68 + oc] = w[(long)oc * Cin + ic0 + ic];
        }
        for (int idx = t; idx < 1024; idx += 256) {
            int ic = idx >> 6, px = idx & 63;
            int c = ic0 + ic;
            float v = in[c * NPIX + p0 + px];
            sIn[idx] = fmaxf(v * Abn[c] + Bbn[c], 0.f);
        }
        __syncthreads();
#pragma unroll
        for (int ic = 0; ic < 16; ic++) {
            float4 a  = *(const float4*)(sW  + ic * 68 + ty * 4);
            float4 xv = *(const float4*)(sIn + ic * 64 + tx * 4);
            float av[4] = {a.x, a.y, a.z, a.w};
            float xa[4] = {xv.x, xv.y, xv.z, xv.w};
#pragma unroll
            for (int r = 0; r < 4; r++)
#pragma unroll
                for (int c = 0; c < 4; c++) acc[r][c] += av[r] * xa[c];
        }
    }
    float sums[4], sqs[4];
#pragma unroll
    for (int r = 0; r < 4; r++) {
        float s = 0.f, q = 0.f;
        float* op = out + (long)(ty * 4 + r) * NPIX + p0 + tx * 4;
#pragma unroll
        for (int c = 0; c < 4; c++) {
            float v = acc[r][c];
            op[c] = v; s += v; q += v * v;
        }
        sums[r] = s; sqs[r] = q;
    }
#pragma unroll
    for (int r = 0; r < 4; r++) {
        float a = sums[r], q = sqs[r];
#pragma unroll
        for (int off = 1; off < 16; off <<= 1) {
            a += __shfl_xor_sync(0xffffffffu, a, off);
            q += __shfl_xor_sync(0xffffffffu, q, off);
        }
        if (tx == 0) {
            int c = ty * 4 + r;
            int slot = b * 64 + blockIdx.x;
            p1[slot * 64 + c] = a;
            p2[slot * 64 + c] = q;
        }
    }
}

// ---------------- fused q/k/v 1x1 projections -> q plain + fp16 K'/V fragment words ----------------
__global__ void __launch_bounds__(256) qkv_kernel(
    const float* __restrict__ brin,
    const float* __restrict__ wq, const float* __restrict__ bq,
    const float* __restrict__ wk, const float* __restrict__ bk,
    const float* __restrict__ wv, const float* __restrict__ bv,
    float* __restrict__ qo, float* __restrict__ kf, float* __restrict__ vf,
    const float* __restrict__ Abase, const float* __restrict__ Bbase)
{
    const int p0  = blockIdx.x * 64;
    const int img = blockIdx.z;
    const int br  = img >> 2;
    const long ib = (long)img * 64 * NPIX;
    const float* A  = Abase + (2 + br) * 256;
    const float* Bb = Bbase + (2 + br) * 256;
    const int t = threadIdx.x, tx = t & 15, ty = t >> 4;

    uint32_t* kfw = (uint32_t*)(kf + (long)img * 262144);  // [j][64 words]
    uint32_t* vfw = (uint32_t*)(vf + (long)img * 131072);  // [d][jg 256][8 words]

    __shared__ float sW [3 * 16 * 64];
    __shared__ float sIn[16 * 64];

    float acc[3][4][4];
#pragma unroll
    for (int m = 0; m < 3; m++)
#pragma unroll
        for (int r = 0; r < 4; r++)
#pragma unroll
            for (int c = 0; c < 4; c++) acc[m][r][c] = 0.f;

    for (int ic0 = 0; ic0 < 64; ic0 += 16) {
        __syncthreads();
        for (int i = t; i < 1024; i += 256) {
            int ic = i >> 6, px = i & 63;
            int c = ic0 + ic;
            float v = brin[ib + (long)c * NPIX + p0 + px];
            sIn[i] = fmaxf(v * A[c] + Bb[c], 0.f);
        }
        for (int i = t; i < 3072; i += 256) {
            int m = i >> 10, r = i & 1023;
            int ic = r & 15, oc = r >> 4;
            const float* wm = (m == 0) ? wq : ((m == 1) ? wk : wv);
            sW[m * 1024 + ic * 64 + oc] = wm[oc * 64 + ic0 + ic];
        }
        __syncthreads();
#pragma unroll
        for (int ic = 0; ic < 16; ic++) {
            float4 xv = *(const float4*)(sIn + ic * 64 + tx * 4);
            float xa[4] = {xv.x, xv.y, xv.z, xv.w};
#pragma unroll
            for (int m = 0; m < 3; m++) {
                float4 a = *(const float4*)(sW + m * 1024 + ic * 64 + ty * 4);
                float av[4] = {a.x, a.y, a.z, a.w};
#pragma unroll
                for (int r = 0; r < 4; r++)
#pragma unroll
                    for (int c = 0; c < 4; c++) acc[m][r][c] += av[r] * xa[c];
            }
        }
    }
    float val[3][4][4];
    const float* bs[3] = {bq, bk, bv};
#pragma unroll
    for (int m = 0; m < 3; m++)
#pragma unroll
        for (int r = 0; r < 4; r++) {
            float bb = bs[m][ty * 4 + r];
#pragma unroll
            for (int ci = 0; ci < 4; ci++) val[m][r][ci] = acc[m][r][ci] + bb;
        }
#pragma unroll
    for (int r = 0; r < 4; r++)
#pragma unroll
        for (int ci = 0; ci < 4; ci++)
            qo[ib + (long)(ty * 4 + r) * NPIX + p0 + tx * 4 + ci] = val[0][r][ci];
#pragma unroll
    for (int m = 0; m < 2; m++) {
#pragma unroll
        for (int rp = 0; rp < 4; rp += 2) {
            int kk0 = (m == 0 ? 64 : 0) + ty * 4 + rp;
            int grp = kk0 >> 4, j2 = (kk0 & 15) >> 1;
            int woff = grp * 8 + ilv(j2);
#pragma unroll
            for (int ci = 0; ci < 4; ci++) {
                int j = p0 + tx * 4 + ci;
                kfw[j * 64 + woff] = pk2h(val[m][rp][ci], val[m][rp + 1][ci]);
            }
        }
    }
#pragma unroll
    for (int r = 0; r < 4; r++) {
        int d = ty * 4 + r;
#pragma unroll
        for (int ci = 0; ci < 4; ci += 2) {
            int j = p0 + tx * 4 + ci;
            int jg = j >> 4, j2 = (j & 15) >> 1;
            vfw[(d * 256 + jg) * 8 + ilv(j2)] = pk2h(val[2][r][ci], val[2][r][ci + 1]);
        }
    }
}

// ---------------- pos table ----------------
__global__ void pos_kernel(const float* __restrict__ rh, const float* __restrict__ rw) {
    int idx = blockIdx.x * blockDim.x + threadIdx.x;
    if (idx >= 64 * NPIX) return;
    int d = idx >> 12, n = idx & 4095, a = n >> 6, bb = n & 63;
    g_pos[idx] = rh[d * 64 + bb] + rw[d * 64 + a];
}

// ================= fp16 k16 fragment-direct flash attention (zero smem) =================
#define LOG2E 1.44269504088896f

__global__ void __launch_bounds__(256, 1) flash_mma_kernel(
    const float* __restrict__ qg, const float* __restrict__ kf,
    const float* __restrict__ vf, float* __restrict__ outg)
{
    const int i0 = blockIdx.x * 128;
    const int b  = blockIdx.y, br = blockIdx.z;
    const int img = br * BATCH + b;
    const float* q = qg + (long)img * 64 * NPIX;
    const uint2* KF2 = (const uint2*)(kf + (long)img * 262144);
    const uint2* VF2 = (const uint2*)(vf + (long)img * 131072);
    float* outp = outg + (long)(b * 256 + br * 64) * NPIX;

    const int t = threadIdx.x;
    const int lane = t & 31, w = t >> 5;
    const int g = lane >> 2, tq = lane & 3;

    uint32_t Qf[8][4];
    {
        int i_r = i0 + w * 16 + g;
#pragma unroll
        for (int kp = 0; kp < 8; kp++) {
            int kc = kp * 16 + 2 * tq;
            const float* pa = (kc     < 64) ? (q + kc * NPIX)       : (g_pos + (kc - 64) * NPIX);
            const float* pb = (kc + 1 < 64) ? (q + (kc + 1) * NPIX) : (g_pos + (kc - 63) * NPIX);
            const float* pc = (kc + 8 < 64) ? (q + (kc + 8) * NPIX) : (g_pos + (kc - 56) * NPIX);
            const float* pd = (kc + 9 < 64) ? (q + (kc + 9) * NPIX) : (g_pos + (kc - 55) * NPIX);
            Qf[kp][0] = pk2h(pa[i_r] * LOG2E,     pb[i_r] * LOG2E);
            Qf[kp][1] = pk2h(pa[i_r + 8] * LOG2E, pb[i_r + 8] * LOG2E);
            Qf[kp][2] = pk2h(pc[i_r] * LOG2E,     pd[i_r] * LOG2E);
            Qf[kp][3] = pk2h(pc[i_r + 8] * LOG2E, pd[i_r + 8] * LOG2E);
        }
    }

    float Oa[8][4];
#pragma unroll
    for (int nt = 0; nt < 8; nt++)
#pragma unroll
        for (int c = 0; c < 4; c++) Oa[nt][c] = 0.f;
    float m0 = -CUDART_INF_F, m1 = -CUDART_INF_F, l0 = 0.f, l1 = 0.f;

    for (int j0 = 0; j0 < NPIX; j0 += 64) {
        float Sa[8][4];
#pragma unroll
        for (int nt = 0; nt < 8; nt++)
#pragma unroll
            for (int c = 0; c < 4; c++) Sa[nt][c] = 0.f;
#pragma unroll
        for (int kp = 0; kp < 8; kp++) {
#pragma unroll
            for (int nt = 0; nt < 8; nt++) {
                uint2 kb = KF2[(j0 + nt * 8 + g) * 32 + kp * 4 + tq];
                mma16h(Sa[nt], Qf[kp], kb.x, kb.y);
            }
        }

        float mx0 = -CUDART_INF_F, mx1 = -CUDART_INF_F;
#pragma unroll
        for (int nt = 0; nt < 8; nt++) {
            mx0 = fmaxf(mx0, fmaxf(Sa[nt][0], Sa[nt][1]));
            mx1 = fmaxf(mx1, fmaxf(Sa[nt][2], Sa[nt][3]));
        }
        mx0 = fmaxf(mx0, __shfl_xor_sync(0xffffffffu, mx0, 1));
        mx0 = fmaxf(mx0, __shfl_xor_sync(0xffffffffu, mx0, 2));
        mx1 = fmaxf(mx1, __shfl_xor_sync(0xffffffffu, mx1, 1));
        mx1 = fmaxf(mx1, __shfl_xor_sync(0xffffffffu, mx1, 2));
        float mn0 = fmaxf(m0, mx0), mn1 = fmaxf(m1, mx1);
        float al0 = ex2f(m0 - mn0), al1 = ex2f(m1 - mn1);

        float su0 = 0.f, su1 = 0.f;
#pragma unroll
        for (int nt = 0; nt < 8; nt++) {
            Sa[nt][0] = ex2f(Sa[nt][0] - mn0);
            Sa[nt][1] = ex2f(Sa[nt][1] - mn0);
            Sa[nt][2] = ex2f(Sa[nt][2] - mn1);
            Sa[nt][3] = ex2f(Sa[nt][3] - mn1);
            su0 += Sa[nt][0] + Sa[nt][1];
            su1 += Sa[nt][2] + Sa[nt][3];
        }
        su0 += __shfl_xor_sync(0xffffffffu, su0, 1);
        su0 += __shfl_xor_sync(0xffffffffu, su0, 2);
        su1 += __shfl_xor_sync(0xffffffffu, su1, 1);
        su1 += __shfl_xor_sync(0xffffffffu, su1, 2);
        l0 = l0 * al0 + su0; l1 = l1 * al1 + su1;
        m0 = mn0; m1 = mn1;
#pragma unroll
        for (int nt = 0; nt < 8; nt++) {
            Oa[nt][0] *= al0; Oa[nt][1] *= al0;
            Oa[nt][2] *= al1; Oa[nt][3] *= al1;
        }

#pragma unroll
        for (int gr = 0; gr < 4; gr++) {
            uint32_t a[4] = {
                pk2h(Sa[2 * gr][0],     Sa[2 * gr][1]),
                pk2h(Sa[2 * gr][2],     Sa[2 * gr][3]),
                pk2h(Sa[2 * gr + 1][0], Sa[2 * gr + 1][1]),
                pk2h(Sa[2 * gr + 1][2], Sa[2 * gr + 1][3])
            };
#pragma unroll
            for (int nt = 0; nt < 8; nt++) {
                uint2 vb = VF2[((nt * 8 + g) * 256 + (j0 >> 4) + gr) * 4 + tq];
                mma16h(Oa[nt], a, vb.x, vb.y);
            }
        }
    }

    float inv0 = 1.f / l0, inv1 = 1.f / l1;
    int pix = i0 + w * 16 + g;
#pragma unroll
    for (int nt = 0; nt < 8; nt++) {
        int d0 = nt * 8 + 2 * tq;
        outp[(long)d0 * NPIX + pix]           = Oa[nt][0] * inv0;
        outp[(long)(d0 + 1) * NPIX + pix]     = Oa[nt][1] * inv0;
        outp[(long)d0 * NPIX + pix + 8]       = Oa[nt][2] * inv1;
        outp[(long)(d0 + 1) * NPIX + pix + 8] = Oa[nt][3] * inv1;
    }
}

// ---------------- host orchestration ----------------
extern "C" void kernel_launch(void* const* d_in, const int* in_sizes, int n_in,
                              void* d_out, int out_size) {
    const float* x      = (const float*)d_in[0];
    const float* dc_w1  = (const float*)d_in[1];
    const float* dc_g1  = (const float*)d_in[3];
    const float* dc_be1 = (const float*)d_in[4];
    const float* dc_w2  = (const float*)d_in[5];
    const float* dc_g2  = (const float*)d_in[7];
    const float* dc_be2 = (const float*)d_in[8];
    const float* aw[4]  = {(const float*)d_in[9],  (const float*)d_in[12],
                           (const float*)d_in[15], (const float*)d_in[18]};
    const float* ag[4]  = {(const float*)d_in[10], (const float*)d_in[13],
                           (const float*)d_in[16], (const float*)d_in[19]};
    const float* ab[4]  = {(const float*)d_in[11], (const float*)d_in[14],
                           (const float*)d_in[17], (const float*)d_in[20]};
    const float* wq = (const float*)d_in[21]; const float* bq = (const float*)d_in[22];
    const float* wk = (const float*)d_in[23]; const float* bk = (const float*)d_in[24];
    const float* wv = (const float*)d_in[25]; const float* bv = (const float*)d_in[26];
    const float* rel_h = (const float*)d_in[27];
    const float* rel_w = (const float*)d_in[28];

    float *buf1, *buf2, *xt0, *xt1, *xt2, *brb, *qb, *kfb, *vfb;
    float *p1, *p2, *An, *Bn, *wt;
    cudaGetSymbolAddress((void**)&buf1, g_buf1);
    cudaGetSymbolAddress((void**)&buf2, g_buf2);
    cudaGetSymbolAddress((void**)&xt0,  g_xt0);
    cudaGetSymbolAddress((void**)&xt1,  g_xt1);
    cudaGetSymbolAddress((void**)&xt2,  g_xt2);
    cudaGetSymbolAddress((void**)&brb,  g_br);
    cudaGetSymbolAddress((void**)&qb,   g_q);
    cudaGetSymbolAddress((void**)&kfb,  g_kf);
    cudaGetSymbolAddress((void**)&vfb,  g_vf);
    cudaGetSymbolAddress((void**)&p1,   g_p1);
    cudaGetSymbolAddress((void**)&p2,   g_p2);
    cudaGetSymbolAddress((void**)&An,   g_An);
    cudaGetSymbolAddress((void**)&Bn,   g_Bn);
    cudaGetSymbolAddress((void**)&wt,   g_wt);

    float* wt1 = wt;                  // conv1: 294912
    float* wt2 = wt + 294912;         // conv2: 589824
    float* wtA = wt + 884736;         // aspp:  3 x 147456

    cudaFuncSetAttribute((const void*)conv_mma_kernel<false>,
                         cudaFuncAttributeMaxDynamicSharedMemorySize, CSM);
    cudaFuncSetAttribute((const void*)conv_mma_kernel<true>,
                         cudaFuncAttributeMaxDynamicSharedMemorySize, CSM);

    // weight prep (fp16 hi/lo, fragment-packed)
    wprep_kernel<<<(256 * 64 * 9 + 255) / 256, 256>>>(dc_w1, wt1, 128, 256);
    wprep_kernel<<<(256 * 128 * 9 + 255) / 256, 256>>>(dc_w2, wt2, 256, 256);
    for (int i = 0; i < 3; i++)
        wprep_kernel<<<(64 * 128 * 9 + 255) / 256, 256>>>(
            aw[i + 1], wtA + (long)i * 147456, 256, 64);

    // mpconv
    maxpool_xt_kernel<<<(BATCH * 64 * NPIX + 255) / 256, 256>>>(x, xt0);
    conv_mma_kernel<false><<<dim3(16, 4, BATCH), 512, CSM>>>(
        xt0, wt1, buf1, 128, p1, p2);
    finalize_kernel<<<256, 128>>>(p1, p2, dc_g1, dc_be1, An + 0, Bn + 0, 256, 64);
    bnprep_xt_kernel<<<(BATCH * 128 * NPIX + 255) / 256, 256>>>(buf1, xt1, An + 0, Bn + 0);
    conv_mma_kernel<false><<<dim3(16, 4, BATCH), 512, CSM>>>(
        xt1, wt2, buf2, 256, p1, p2);
    finalize_kernel<<<256, 128>>>(p1, p2, dc_g2, dc_be2, An + 256, Bn + 256, 256, 64);
    bnprep_xt_kernel<<<(BATCH * 128 * NPIX + 255) / 256, 256>>>(buf2, xt2, An + 256, Bn + 256);

    // ASPP dilated branches fused; 1x1 branch exact
    conv_mma_kernel<true><<<dim3(16, 3, BATCH), 512, CSM>>>(
        xt2, wtA, brb + (long)BATCH * 64 * NPIX, 256, p1, p2);
    for (int i = 0; i < 3; i++)
        finalize_kernel<<<64, 128>>>(p1 + i * 8192, p2 + i * 8192, ag[i + 1], ab[i + 1],
                                     An + (3 + i) * 256, Bn + (3 + i) * 256, 64, 64);
    conv1x1_bn_kernel<<<dim3(64, 1, BATCH), 256>>>(
        buf2, aw[0], brb, 256, An + 256, Bn + 256, p1 + 32768, p2 + 32768);
    finalize_kernel<<<64, 128>>>(p1 + 32768, p2 + 32768, ag[0], ab[0],
                                 An + 2 * 256, Bn + 2 * 256, 64, 256);

    // fused qkv (fp16 fragment emission) + pos
    qkv_kernel<<<dim3(64, 1, 16), 256>>>(brb, wq, bq, wk, bk, wv, bv,
                                         qb, kfb, vfb, An, Bn);
    pos_kernel<<<(64 * NPIX + 255) / 256, 256>>>(rel_h, rel_w);

    // fp16 flash attention (no smem) -> concat output
    flash_mma_kernel<<<dim3(32, BATCH, 4), 256>>>(qb, kfb, vfb, (float*)d_out);
}

// round 17
// speedup vs baseline: 1.7033x; 1.0033x over previous
#include <cuda_runtime.h>
#include <cuda_fp16.h>
#include <math_constants.h>
#include <stdint.h>

#define BATCH 4
#define NPIX 4096   // 64*64

// ---------------- scratch (device globals; no cudaMalloc allowed) ----------------
__device__ float g_buf1 [BATCH * 256 * NPIX];      // conv1 raw out (fp32)
__device__ float g_buf2 [BATCH * 256 * NPIX];      // conv2 raw out (fp32)
__device__ float g_xt0  [BATCH * 8  * NPIX * 8];   // conv1 input packed fp16
__device__ float g_xt1  [BATCH * 16 * NPIX * 8];   // conv2 input packed
__device__ float g_xt2  [BATCH * 16 * NPIX * 8];   // aspp  input packed
__device__ float g_br  [4 * BATCH * 64 * NPIX];
__device__ float g_q   [4 * BATCH * 64 * NPIX];    // plain q
__device__ float g_kf  [16 * 4096 * 64];           // K' (128-dim) packed fp16 words
__device__ float g_vf  [16 * 64 * 256 * 8];        // V packed fp16 words
__device__ float g_pos [64 * NPIX];
__device__ float g_p1  [256 * 256];
__device__ float g_p2  [256 * 256];
__device__ float g_An  [6 * 256];
__device__ float g_Bn  [6 * 256];
__device__ float g_wt  [1327104];   // packed fp16 hi/lo conv weights

__device__ __forceinline__ float ex2f(float x) {
    float y;
    asm("ex2.approx.ftz.f32 %0, %1;" : "=f"(y) : "f"(x));
    return y;
}
__device__ __forceinline__ void mma16h(float d[4], const uint32_t a[4],
                                       uint32_t b0, uint32_t b1) {
    asm volatile(
        "mma.sync.aligned.m16n8k16.row.col.f32.f16.f16.f32 "
        "{%0,%1,%2,%3},{%4,%5,%6,%7},{%8,%9},{%0,%1,%2,%3};"
        : "+f"(d[0]), "+f"(d[1]), "+f"(d[2]), "+f"(d[3])
        : "r"(a[0]), "r"(a[1]), "r"(a[2]), "r"(a[3]), "r"(b0), "r"(b1));
}
__device__ __forceinline__ int ilv(int klo) { return (klo & 3) * 2 + (klo >> 2); }
__device__ __forceinline__ uint32_t pk2h(float a, float b) {
    __half2 t = __floats2half2_rn(a, b);
    return *reinterpret_cast<uint32_t*>(&t);
}
__device__ __forceinline__ float hfhi(float x) {
    return __half2float(__float2half(x));
}

// ---------------- maxpool 2x2 -> packed fp16 channel-pair layout ----------------
__global__ void maxpool_xt_kernel(const float* __restrict__ x, float* __restrict__ xt) {
    int idx = blockIdx.x * blockDim.x + threadIdx.x;
    if (idx >= BATCH * 64 * NPIX) return;
    int pix = idx & 4095, rest = idx >> 12;
    int cp = rest & 63, b = rest >> 6;
    int y = pix >> 6, xx = pix & 63;
    float v[2];
#pragma unroll
    for (int e = 0; e < 2; e++) {
        const float* src = x + ((long)(b * 128 + 2 * cp + e) * 128 + 2 * y) * 128 + 2 * xx;
        v[e] = fmaxf(fmaxf(src[0], src[1]), fmaxf(src[128], src[129]));
    }
    int chunk = cp >> 3, j = cp & 7;
    long base = (((long)(b * 8 + chunk)) * 4096 + pix) * 8 + ilv(j);
    ((uint32_t*)xt)[base] = pk2h(v[0], v[1]);
}

// ---------------- bnprep: raw fp32 [c][pix] -> relu(BN) -> packed fp16 ----------------
__global__ void bnprep_xt_kernel(const float* __restrict__ in, float* __restrict__ xt,
                                 const float* __restrict__ A, const float* __restrict__ B) {
    int idx = blockIdx.x * blockDim.x + threadIdx.x;
    if (idx >= BATCH * 128 * NPIX) return;
    int pix = idx & 4095, rest = idx >> 12;
    int cp = rest & 127, b = rest >> 7;
    int c0 = 2 * cp;
    float v0 = fmaxf(in[((long)(b * 256 + c0)) * NPIX + pix] * A[c0] + B[c0], 0.f);
    float v1 = fmaxf(in[((long)(b * 256 + c0 + 1)) * NPIX + pix] * A[c0 + 1] + B[c0 + 1], 0.f);
    int chunk = cp >> 3, j = cp & 7;
    long base = (((long)(b * 16 + chunk)) * 4096 + pix) * 8 + ilv(j);
    ((uint32_t*)xt)[base] = pk2h(v0, v1);
}

// ---------------- weight prep: OIHW -> [ocg64][chunk16ic][hi/lo][tap][ocl][8 words] ----------------
__global__ void wprep_kernel(const float* __restrict__ W, float* __restrict__ dst,
                             int Cin, int Cout) {
    int idx = blockIdx.x * 256 + threadIdx.x;
    int cp = Cin >> 1;
    int total = Cout * cp * 9;
    if (idx >= total) return;
    int tap = idx % 9;
    int rem = idx / 9;
    int jp  = rem % cp;
    int oc  = rem / cp;
    float w0 = W[((long)oc * Cin + 2 * jp) * 9 + tap];
    float w1 = W[((long)oc * Cin + 2 * jp + 1) * 9 + tap];
    float h0 = hfhi(w0), h1 = hfhi(w1);
    int ocg = oc >> 6, ocl = oc & 63, chunk = jp >> 3, j = jp & 7;
    int nch = Cin >> 4;
    long base = (long)(ocg * nch + chunk) * 9216;
    uint32_t* d = (uint32_t*)dst;
    d[base +        (tap * 64 + ocl) * 8 + ilv(j)] = pk2h(h0, h1);
    d[base + 4608 + (tap * 64 + ocl) * 8 + ilv(j)] = pk2h(w0 - h0, w1 - h1);
}

// ======== fp16 2-term tensor-core 3x3 dilated conv, 2-stage cp.async pipeline ========
#define SINW  8448
#define WW    9216
#define STAGEW 17664
#define CSM   ((2 * STAGEW + 1024) * 4)
template<bool AS>
__global__ void __launch_bounds__(512, 1) conv_mma_kernel(
    const float* __restrict__ in, const float* __restrict__ wtbase,
    float* __restrict__ outbase, int Cin,
    float* __restrict__ p1base, float* __restrict__ p2base)
{
    extern __shared__ float sm[];
    float* sRS = sm + 2 * STAGEW;
    float* sRQ = sRS + 512;

    const int ytile = blockIdx.x;
    const int b     = blockIdx.z;
    const int nchunk = Cin >> 4;
    int dil, ocg, Cout;
    const float* wt;
    float* out;
    float *p1, *p2;
    if (AS) {
        int br = blockIdx.y;
        dil = 3 * (br + 1); ocg = 0; Cout = 64;
        wt  = wtbase + (long)br * 147456;
        out = outbase + ((long)br * BATCH + b) * 64 * NPIX;
        p1  = p1base + br * 8192;
        p2  = p2base + br * 8192;
    } else {
        dil = 1; ocg = blockIdx.y; Cout = gridDim.y * 64;
        wt  = wtbase + (long)ocg * nchunk * WW;
        out = outbase + (long)b * Cout * NPIX;
        p1  = p1base; p2 = p2base;
    }
    in += (long)b * nchunk * 32768;

    const int t = threadIdx.x, lane = t & 31, w = t >> 5;
    const int g = lane >> 2, tq = lane & 3;
    const int mwarp = w >> 3;
    const int yr    = (w >> 1) & 3;
    const int nh    = w & 1;
    const int y0    = ytile * 4;

    const uint32_t smb = (uint32_t)__cvta_generic_to_shared(sm);

    for (int i = t; i < SINW; i += 512) { sm[i] = 0.f; sm[STAGEW + i] = 0.f; }
    __syncthreads();

    auto issue = [&](int c, int s) {
        const uint32_t stb = smb + (uint32_t)(s * STAGEW * 4);
        const float4* ws = (const float4*)(wt + (long)c * WW);
        const uint32_t swu = stb + (uint32_t)(SINW * 4);
        for (int i = t; i < 2304; i += 512)
            asm volatile("cp.async.cg.shared.global [%0], [%1], 16;\n"
                         :: "r"(swu + i * 16), "l"(ws + i));
#pragma unroll
        for (int e = t; e < 1536; e += 512) {
            int fx  = e & 127;
            int r   = e >> 7;
            int ky = r >> 2, yri = r & 3;
            int ry = y0 + yri + (ky - 1) * dil;
            int ok = (ry >= 0 && ry < 64);
            uint32_t dst = stb + (uint32_t)(((ky * 4 + yri) * 704 + 96) * 4 + fx * 16);
            const float4* src = (const float4*)(in + ((long)c * 4096 +
                                                      (ok ? ry : 0) * 64) * 8) + fx;
            int ssz = ok ? 16 : 0;
            asm volatile("cp.async.cg.shared.global [%0], [%1], 16, %2;\n"
                         :: "r"(dst), "l"(src), "r"(ssz));
        }
        asm volatile("cp.async.commit_group;\n");
    };

    float acc[2][4][4];
#pragma unroll
    for (int mf = 0; mf < 2; mf++)
#pragma unroll
        for (int nt = 0; nt < 4; nt++)
#pragma unroll
            for (int c = 0; c < 4; c++) acc[mf][nt][c] = 0.f;

    issue(0, 0);

    for (int chunk = 0; chunk < nchunk; chunk++) {
        const int s = chunk & 1;
        if (chunk + 1 < nchunk) {
            issue(chunk + 1, s ^ 1);
            asm volatile("cp.async.wait_group 1;\n" ::: "memory");
        } else {
            asm volatile("cp.async.wait_group 0;\n" ::: "memory");
        }
        __syncthreads();

        const uint32_t* sIn = (const uint32_t*)sm + s * STAGEW;
        const uint32_t* sW  = sIn + SINW;

#pragma unroll
        for (int tap = 0; tap < 9; tap++) {
            const int ky = tap / 3, kx = tap % 3;
            const uint32_t* wb = sW + (tap * 64 + mwarp * 32 + g) * 8 + 2 * tq;
            uint2 h0  = *(const uint2*)(wb);
            uint2 h0b = *(const uint2*)(wb + 64);
            uint2 h1  = *(const uint2*)(wb + 128);
            uint2 h1b = *(const uint2*)(wb + 192);
            uint2 l0  = *(const uint2*)(wb + 4608);
            uint2 l0b = *(const uint2*)(wb + 4672);
            uint2 l1  = *(const uint2*)(wb + 4736);
            uint2 l1b = *(const uint2*)(wb + 4800);
            uint32_t aH0[4] = {h0.x, h0b.x, h0.y, h0b.y};
            uint32_t aH1[4] = {h1.x, h1b.x, h1.y, h1b.y};
            uint32_t aL0[4] = {l0.x, l0b.x, l0.y, l0b.y};
            uint32_t aL1[4] = {l1.x, l1b.x, l1.y, l1b.y};
            const int rowoff = (ky * 4 + yr) * 704 +
                               (12 + nh * 32 + g + (kx - 1) * dil) * 8 + 2 * tq;
#pragma unroll
            for (int nt = 0; nt < 4; nt++) {
                uint2 bh = *(const uint2*)(sIn + rowoff + nt * 64);
                mma16h(acc[0][nt], aH0, bh.x, bh.y);
                mma16h(acc[1][nt], aH1, bh.x, bh.y);
                mma16h(acc[0][nt], aL0, bh.x, bh.y);
                mma16h(acc[1][nt], aL1, bh.x, bh.y);
            }
        }
        __syncthreads();
    }

    // ---- epilogue: vectorized store + BN partials ----
    float s_[2][2] = {{0.f, 0.f}, {0.f, 0.f}};
    float q_[2][2] = {{0.f, 0.f}, {0.f, 0.f}};
    const int ocb = ocg * 64 + mwarp * 32;
#pragma unroll
    for (int mf = 0; mf < 2; mf++) {
        int oc = ocb + mf * 16 + g;
#pragma unroll
        for (int nt = 0; nt < 4; nt++) {
            int gx = (y0 + yr) * 64 + nh * 32 + nt * 8 + 2 * tq;
            float c0 = acc[mf][nt][0], c1 = acc[mf][nt][1];
            float c2 = acc[mf][nt][2], c3 = acc[mf][nt][3];
            *(float2*)(out + (long)oc * NPIX + gx)       = make_float2(c0, c1);
            *(float2*)(out + (long)(oc + 8) * NPIX + gx) = make_float2(c2, c3);
            s_[mf][0] += c0 + c1; q_[mf][0] += c0 * c0 + c1 * c1;
            s_[mf][1] += c2 + c3; q_[mf][1] += c2 * c2 + c3 * c3;
        }
    }
#pragma unroll
    for (int mf = 0; mf < 2; mf++)
#pragma unroll
        for (int ro = 0; ro < 2; ro++) {
            float a = s_[mf][ro], qq = q_[mf][ro];
            a  += __shfl_xor_sync(0xffffffffu, a, 1);
            qq += __shfl_xor_sync(0xffffffffu, qq, 1);
            a  += __shfl_xor_sync(0xffffffffu, a, 2);
            qq += __shfl_xor_sync(0xffffffffu, qq, 2);
            if (tq == 0) {
                sRS[w * 32 + mf * 16 + ro * 8 + g] = a;
                sRQ[w * 32 + mf * 16 + ro * 8 + g] = qq;
            }
        }
    __syncthreads();
    if (t < 64) {
        int mw = t >> 5, cl = t & 31;
        float a = 0.f, qq = 0.f;
#pragma unroll
        for (int j = 0; j < 8; j++) {
            a  += sRS[(mw * 8 + j) * 32 + cl];
            qq += sRQ[(mw * 8 + j) * 32 + cl];
        }
        int slot = b * 16 + ytile;
        p1[slot * Cout + ocg * 64 + t] = a;
        p2[slot * Cout + ocg * 64 + t] = qq;
    }
}

// ---------------- BN finalize ----------------
__global__ void finalize_kernel(const float* __restrict__ p1, const float* __restrict__ p2,
                                const float* __restrict__ g, const float* __restrict__ be,
                                float* __restrict__ A, float* __restrict__ B,
                                int C, int nslots) {
    const int c = blockIdx.x, t = threadIdx.x;
    float s = 0.f, q = 0.f;
    for (int slot = t; slot < nslots; slot += 128) {
        s += p1[slot * C + c];
        q += p2[slot * C + c];
    }
    __shared__ float rs[4], rq[4];
#pragma unroll
    for (int off = 16; off; off >>= 1) {
        s += __shfl_down_sync(0xffffffffu, s, off);
        q += __shfl_down_sync(0xffffffffu, q, off);
    }
    int lane = t & 31, wp = t >> 5;
    if (!lane) { rs[wp] = s; rq[wp] = q; }
    __syncthreads();
    if (t == 0) {
        s = rs[0] + rs[1] + rs[2] + rs[3];
        q = rq[0] + rq[1] + rq[2] + rq[3];
        const float inv = 1.f / (float)(BATCH * NPIX);
        float mean = s * inv;
        float var  = q * inv - mean * mean;
        float a = g[c] * rsqrtf(var + 1e-5f);
        A[c] = a;
        B[c] = be[c] - mean * a;
    }
}

// ---------------- 1x1 conv Cout=64 with input-BN + stats (aspp1, exact fp32) ----------------
__global__ void __launch_bounds__(256) conv1x1_bn_kernel(
    const float* __restrict__ in, const float* __restrict__ w,
    float* __restrict__ out, int Cin,
    const float* __restrict__ Abn, const float* __restrict__ Bbn,
    float* __restrict__ p1, float* __restrict__ p2)
{
    const int p0 = blockIdx.x * 64;
    const int b  = blockIdx.z;
    in  += (long)b * Cin * NPIX;
    out += (long)b * 64  * NPIX;
    const int t = threadIdx.x, tx = t & 15, ty = t >> 4;

    __shared__ float sW [16 * 68];
    __shared__ float sIn[16 * 64];

    float acc[4][4];
#pragma unroll
    for (int r = 0; r < 4; r++)
#pragma unroll
        for (int c = 0; c < 4; c++) acc[r][c] = 0.f;

    for (int ic0 = 0; ic0 < Cin; ic0 += 16) {
        __syncthreads();
        for (int idx = t; idx < 1024; idx += 256) {
            int ic = idx & 15, oc = idx >> 4;
            sW[ic * 68 + oc] = w[(long)oc * Cin + ic0 + ic];
        }
        for (int idx = t; idx < 1024; idx += 256) {
            int ic = idx >> 6, px = idx & 63;
            int c = ic0 + ic;
            float v = in[c * NPIX + p0 + px];
            sIn[idx] = fmaxf(v * Abn[c] + Bbn[c], 0.f);
        }
        __syncthreads();
#pragma unroll
        for (int ic = 0; ic < 16; ic++) {
            float4 a  = *(const float4*)(sW  + ic * 68 + ty * 4);
            float4 xv = *(const float4*)(sIn + ic * 64 + tx * 4);
            float av[4] = {a.x, a.y, a.z, a.w};
            float xa[4] = {xv.x, xv.y, xv.z, xv.w};
#pragma unroll
            for (int r = 0; r < 4; r++)
#pragma unroll
                for (int c = 0; c < 4; c++) acc[r][c] += av[r] * xa[c];
        }
    }
    float sums[4], sqs[4];
#pragma unroll
    for (int r = 0; r < 4; r++) {
        float s = 0.f, q = 0.f;
        float* op = out + (long)(ty * 4 + r) * NPIX + p0 + tx * 4;
#pragma unroll
        for (int c = 0; c < 4; c++) {
            float v = acc[r][c];
            op[c] = v; s += v; q += v * v;
        }
        sums[r] = s; sqs[r] = q;
    }
#pragma unroll
    for (int r = 0; r < 4; r++) {
        float a = sums[r], q = sqs[r];
#pragma unroll
        for (int off = 1; off < 16; off <<= 1) {
            a += __shfl_xor_sync(0xffffffffu, a, off);
            q += __shfl_xor_sync(0xffffffffu, q, off);
        }
        if (tx == 0) {
            int c = ty * 4 + r;
            int slot = b * 64 + blockIdx.x;
            p1[slot * 64 + c] = a;
            p2[slot * 64 + c] = q;
        }
    }
}

// ---------------- fused q/k/v 1x1 projections -> q plain + fp16 K'/V fragment words ----------------
__global__ void __launch_bounds__(256) qkv_kernel(
    const float* __restrict__ brin,
    const float* __restrict__ wq, const float* __restrict__ bq,
    const float* __restrict__ wk, const float* __restrict__ bk,
    const float* __restrict__ wv, const float* __restrict__ bv,
    float* __restrict__ qo, float* __restrict__ kf, float* __restrict__ vf,
    const float* __restrict__ Abase, const float* __restrict__ Bbase)
{
    const int p0  = blockIdx.x * 64;
    const int img = blockIdx.z;
    const int br  = img >> 2;
    const long ib = (long)img * 64 * NPIX;
    const float* A  = Abase + (2 + br) * 256;
    const float* Bb = Bbase + (2 + br) * 256;
    const int t = threadIdx.x, tx = t & 15, ty = t >> 4;

    uint32_t* kfw = (uint32_t*)(kf + (long)img * 262144);  // [j][64 words]
    uint32_t* vfw = (uint32_t*)(vf + (long)img * 131072);  // [d][jg 256][8 words]

    __shared__ float sW [3 * 16 * 64];
    __shared__ float sIn[16 * 64];

    float acc[3][4][4];
#pragma unroll
    for (int m = 0; m < 3; m++)
#pragma unroll
        for (int r = 0; r < 4; r++)
#pragma unroll
            for (int c = 0; c < 4; c++) acc[m][r][c] = 0.f;

    for (int ic0 = 0; ic0 < 64; ic0 += 16) {
        __syncthreads();
        for (int i = t; i < 1024; i += 256) {
            int ic = i >> 6, px = i & 63;
            int c = ic0 + ic;
            float v = brin[ib + (long)c * NPIX + p0 + px];
            sIn[i] = fmaxf(v * A[c] + Bb[c], 0.f);
        }
        for (int i = t; i < 3072; i += 256) {
            int m = i >> 10, r = i & 1023;
            int ic = r & 15, oc = r >> 4;
            const float* wm = (m == 0) ? wq : ((m == 1) ? wk : wv);
            sW[m * 1024 + ic * 64 + oc] = wm[oc * 64 + ic0 + ic];
        }
        __syncthreads();
#pragma unroll
        for (int ic = 0; ic < 16; ic++) {
            float4 xv = *(const float4*)(sIn + ic * 64 + tx * 4);
            float xa[4] = {xv.x, xv.y, xv.z, xv.w};
#pragma unroll
            for (int m = 0; m < 3; m++) {
                float4 a = *(const float4*)(sW + m * 1024 + ic * 64 + ty * 4);
                float av[4] = {a.x, a.y, a.z, a.w};
#pragma unroll
                for (int r = 0; r < 4; r++)
#pragma unroll
                    for (int c = 0; c < 4; c++) acc[m][r][c] += av[r] * xa[c];
            }
        }
    }
    float val[3][4][4];
    const float* bs[3] = {bq, bk, bv};
#pragma unroll
    for (int m = 0; m < 3; m++)
#pragma unroll
        for (int r = 0; r < 4; r++) {
            float bb = bs[m][ty * 4 + r];
#pragma unroll
            for (int ci = 0; ci < 4; ci++) val[m][r][ci] = acc[m][r][ci] + bb;
        }
    // plain q
#pragma unroll
    for (int r = 0; r < 4; r++)
#pragma unroll
        for (int ci = 0; ci < 4; ci++)
            qo[ib + (long)(ty * 4 + r) * NPIX + p0 + tx * 4 + ci] = val[0][r][ci];
    // K' words: kk = oc (from k) and 64+oc (from q); pack consecutive-oc pairs
#pragma unroll
    for (int m = 0; m < 2; m++) {
#pragma unroll
        for (int rp = 0; rp < 4; rp += 2) {
            int kk0 = (m == 0 ? 64 : 0) + ty * 4 + rp;
            int grp = kk0 >> 4, j2 = (kk0 & 15) >> 1;
            int woff = grp * 8 + ilv(j2);
#pragma unroll
            for (int ci = 0; ci < 4; ci++) {
                int j = p0 + tx * 4 + ci;
                kfw[j * 64 + woff] = pk2h(val[m][rp][ci], val[m][rp + 1][ci]);
            }
        }
    }
    // V words: pack consecutive-j pairs
#pragma unroll
    for (int r = 0; r < 4; r++) {
        int d = ty * 4 + r;
#pragma unroll
        for (int ci = 0; ci < 4; ci += 2) {
            int j = p0 + tx * 4 + ci;
            int jg = j >> 4, j2 = (j & 15) >> 1;
            vfw[(d * 256 + jg) * 8 + ilv(j2)] = pk2h(val[2][r][ci], val[2][r][ci + 1]);
        }
    }
}

// ---------------- pos table ----------------
__global__ void pos_kernel(const float* __restrict__ rh, const float* __restrict__ rw) {
    int idx = blockIdx.x * blockDim.x + threadIdx.x;
    if (idx >= 64 * NPIX) return;
    int d = idx >> 12, n = idx & 4095, a = n >> 6, bb = n & 63;
    g_pos[idx] = rh[d * 64 + bb] + rw[d * 64 + a];
}

// ================= fp16 k16 fragment-direct flash attention (zero smem, 2 CTAs/SM) =================
#define LOG2E 1.44269504088896f

__global__ void __launch_bounds__(256, 2) flash_mma_kernel(
    const float* __restrict__ qg, const float* __restrict__ kf,
    const float* __restrict__ vf, float* __restrict__ outg)
{
    const int i0 = blockIdx.x * 128;
    const int b  = blockIdx.y, br = blockIdx.z;
    const int img = br * BATCH + b;
    const float* q = qg + (long)img * 64 * NPIX;
    const uint2* KF2 = (const uint2*)(kf + (long)img * 262144);
    const uint2* VF2 = (const uint2*)(vf + (long)img * 131072);
    float* outp = outg + (long)(b * 256 + br * 64) * NPIX;

    const int t = threadIdx.x;
    const int lane = t & 31, w = t >> 5;
    const int g = lane >> 2, tq = lane & 3;

    uint32_t Qf[8][4];
    {
        int i_r = i0 + w * 16 + g;
#pragma unroll
        for (int kp = 0; kp < 8; kp++) {
            int kc = kp * 16 + 2 * tq;
            const float* pa = (kc     < 64) ? (q + kc * NPIX)       : (g_pos + (kc - 64) * NPIX);
            const float* pb = (kc + 1 < 64) ? (q + (kc + 1) * NPIX) : (g_pos + (kc - 63) * NPIX);
            const float* pc = (kc + 8 < 64) ? (q + (kc + 8) * NPIX) : (g_pos + (kc - 56) * NPIX);
            const float* pd = (kc + 9 < 64) ? (q + (kc + 9) * NPIX) : (g_pos + (kc - 55) * NPIX);
            Qf[kp][0] = pk2h(pa[i_r] * LOG2E,     pb[i_r] * LOG2E);
            Qf[kp][1] = pk2h(pa[i_r + 8] * LOG2E, pb[i_r + 8] * LOG2E);
            Qf[kp][2] = pk2h(pc[i_r] * LOG2E,     pd[i_r] * LOG2E);
            Qf[kp][3] = pk2h(pc[i_r + 8] * LOG2E, pd[i_r + 8] * LOG2E);
        }
    }

    float Oa[8][4];
#pragma unroll
    for (int nt = 0; nt < 8; nt++)
#pragma unroll
        for (int c = 0; c < 4; c++) Oa[nt][c] = 0.f;
    float m0 = -CUDART_INF_F, m1 = -CUDART_INF_F, l0 = 0.f, l1 = 0.f;

    for (int j0 = 0; j0 < NPIX; j0 += 64) {
        float Sa[8][4];
#pragma unroll
        for (int nt = 0; nt < 8; nt++)
#pragma unroll
            for (int c = 0; c < 4; c++) Sa[nt][c] = 0.f;
#pragma unroll
        for (int kp = 0; kp < 8; kp++) {
#pragma unroll
            for (int nt = 0; nt < 8; nt++) {
                uint2 kb = KF2[(j0 + nt * 8 + g) * 32 + kp * 4 + tq];
                mma16h(Sa[nt], Qf[kp], kb.x, kb.y);
            }
        }

        float mx0 = -CUDART_INF_F, mx1 = -CUDART_INF_F;
#pragma unroll
        for (int nt = 0; nt < 8; nt++) {
            mx0 = fmaxf(mx0, fmaxf(Sa[nt][0], Sa[nt][1]));
            mx1 = fmaxf(mx1, fmaxf(Sa[nt][2], Sa[nt][3]));
        }
        mx0 = fmaxf(mx0, __shfl_xor_sync(0xffffffffu, mx0, 1));
        mx0 = fmaxf(mx0, __shfl_xor_sync(0xffffffffu, mx0, 2));
        mx1 = fmaxf(mx1, __shfl_xor_sync(0xffffffffu, mx1, 1));
        mx1 = fmaxf(mx1, __shfl_xor_sync(0xffffffffu, mx1, 2));
        float mn0 = fmaxf(m0, mx0), mn1 = fmaxf(m1, mx1);
        float al0 = ex2f(m0 - mn0), al1 = ex2f(m1 - mn1);

        float su0 = 0.f, su1 = 0.f;
#pragma unroll
        for (int nt = 0; nt < 8; nt++) {
            Sa[nt][0] = ex2f(Sa[nt][0] - mn0);
            Sa[nt][1] = ex2f(Sa[nt][1] - mn0);
            Sa[nt][2] = ex2f(Sa[nt][2] - mn1);
            Sa[nt][3] = ex2f(Sa[nt][3] - mn1);
            su0 += Sa[nt][0] + Sa[nt][1];
            su1 += Sa[nt][2] + Sa[nt][3];
        }
        su0 += __shfl_xor_sync(0xffffffffu, su0, 1);
        su0 += __shfl_xor_sync(0xffffffffu, su0, 2);
        su1 += __shfl_xor_sync(0xffffffffu, su1, 1);
        su1 += __shfl_xor_sync(0xffffffffu, su1, 2);
        l0 = l0 * al0 + su0; l1 = l1 * al1 + su1;
        m0 = mn0; m1 = mn1;
#pragma unroll
        for (int nt = 0; nt < 8; nt++) {
            Oa[nt][0] *= al0; Oa[nt][1] *= al0;
            Oa[nt][2] *= al1; Oa[nt][3] *= al1;
        }

#pragma unroll
        for (int gr = 0; gr < 4; gr++) {
            uint32_t a[4] = {
                pk2h(Sa[2 * gr][0],     Sa[2 * gr][1]),
                pk2h(Sa[2 * gr][2],     Sa[2 * gr][3]),
                pk2h(Sa[2 * gr + 1][0], Sa[2 * gr + 1][1]),
                pk2h(Sa[2 * gr + 1][2], Sa[2 * gr + 1][3])
            };
#pragma unroll
            for (int nt = 0; nt < 8; nt++) {
                uint2 vb = VF2[((nt * 8 + g) * 256 + (j0 >> 4) + gr) * 4 + tq];
                mma16h(Oa[nt], a, vb.x, vb.y);
            }
        }
    }

    float inv0 = 1.f / l0, inv1 = 1.f / l1;
    int pix = i0 + w * 16 + g;
#pragma unroll
    for (int nt = 0; nt < 8; nt++) {
        int d0 = nt * 8 + 2 * tq;
        outp[(long)d0 * NPIX + pix]           = Oa[nt][0] * inv0;
        outp[(long)(d0 + 1) * NPIX + pix]     = Oa[nt][1] * inv0;
        outp[(long)d0 * NPIX + pix + 8]       = Oa[nt][2] * inv1;
        outp[(long)(d0 + 1) * NPIX + pix + 8] = Oa[nt][3] * inv1;
    }
}

// ---------------- host orchestration ----------------
extern "C" void kernel_launch(void* const* d_in, const int* in_sizes, int n_in,
                              void* d_out, int out_size) {
    const float* x      = (const float*)d_in[0];
    const float* dc_w1  = (const float*)d_in[1];
    const float* dc_g1  = (const float*)d_in[3];
    const float* dc_be1 = (const float*)d_in[4];
    const float* dc_w2  = (const float*)d_in[5];
    const float* dc_g2  = (const float*)d_in[7];
    const float* dc_be2 = (const float*)d_in[8];
    const float* aw[4]  = {(const float*)d_in[9],  (const float*)d_in[12],
                           (const float*)d_in[15], (const float*)d_in[18]};
    const float* ag[4]  = {(const float*)d_in[10], (const float*)d_in[13],
                           (const float*)d_in[16], (const float*)d_in[19]};
    const float* ab[4]  = {(const float*)d_in[11], (const float*)d_in[14],
                           (const float*)d_in[17], (const float*)d_in[20]};
    const float* wq = (const float*)d_in[21]; const float* bq = (const float*)d_in[22];
    const float* wk = (const float*)d_in[23]; const float* bk = (const float*)d_in[24];
    const float* wv = (const float*)d_in[25]; const float* bv = (const float*)d_in[26];
    const float* rel_h = (const float*)d_in[27];
    const float* rel_w = (const float*)d_in[28];

    float *buf1, *buf2, *xt0, *xt1, *xt2, *brb, *qb, *kfb, *vfb;
    float *p1, *p2, *An, *Bn, *wt;
    cudaGetSymbolAddress((void**)&buf1, g_buf1);
    cudaGetSymbolAddress((void**)&buf2, g_buf2);
    cudaGetSymbolAddress((void**)&xt0,  g_xt0);
    cudaGetSymbolAddress((void**)&xt1,  g_xt1);
    cudaGetSymbolAddress((void**)&xt2,  g_xt2);
    cudaGetSymbolAddress((void**)&brb,  g_br);
    cudaGetSymbolAddress((void**)&qb,   g_q);
    cudaGetSymbolAddress((void**)&kfb,  g_kf);
    cudaGetSymbolAddress((void**)&vfb,  g_vf);
    cudaGetSymbolAddress((void**)&p1,   g_p1);
    cudaGetSymbolAddress((void**)&p2,   g_p2);
    cudaGetSymbolAddress((void**)&An,   g_An);
    cudaGetSymbolAddress((void**)&Bn,   g_Bn);
    cudaGetSymbolAddress((void**)&wt,   g_wt);

    float* wt1 = wt;                  // conv1: 294912
    float* wt2 = wt + 294912;         // conv2: 589824
    float* wtA = wt + 884736;         // aspp:  3 x 147456

    cudaFuncSetAttribute((const void*)conv_mma_kernel<false>,
                         cudaFuncAttributeMaxDynamicSharedMemorySize, CSM);
    cudaFuncSetAttribute((const void*)conv_mma_kernel<true>,
                         cudaFuncAttributeMaxDynamicSharedMemorySize, CSM);

    // weight prep (fp16 hi/lo, fragment-packed)
    wprep_kernel<<<(256 * 64 * 9 + 255) / 256, 256>>>(dc_w1, wt1, 128, 256);
    wprep_kernel<<<(256 * 128 * 9 + 255) / 256, 256>>>(dc_w2, wt2, 256, 256);
    for (int i = 0; i < 3; i++)
        wprep_kernel<<<(64 * 128 * 9 + 255) / 256, 256>>>(
            aw[i + 1], wtA + (long)i * 147456, 256, 64);

    // mpconv
    maxpool_xt_kernel<<<(BATCH * 64 * NPIX + 255) / 256, 256>>>(x, xt0);
    conv_mma_kernel<false><<<dim3(16, 4, BATCH), 512, CSM>>>(
        xt0, wt1, buf1, 128, p1, p2);
    finalize_kernel<<<256, 128>>>(p1, p2, dc_g1, dc_be1, An + 0, Bn + 0, 256, 64);
    bnprep_xt_kernel<<<(BATCH * 128 * NPIX + 255) / 256, 256>>>(buf1, xt1, An + 0, Bn + 0);
    conv_mma_kernel<false><<<dim3(16, 4, BATCH), 512, CSM>>>(
        xt1, wt2, buf2, 256, p1, p2);
    finalize_kernel<<<256, 128>>>(p1, p2, dc_g2, dc_be2, An + 256, Bn + 256, 256, 64);
    bnprep_xt_kernel<<<(BATCH * 128 * NPIX + 255) / 256, 256>>>(buf2, xt2, An + 256, Bn + 256);

    // ASPP dilated branches fused; 1x1 branch exact
    conv_mma_kernel<true><<<dim3(16, 3, BATCH), 512, CSM>>>(
        xt2, wtA, brb + (long)BATCH * 64 * NPIX, 256, p1, p2);
    for (int i = 0; i < 3; i++)
        finalize_kernel<<<64, 128>>>(p1 + i * 8192, p2 + i * 8192, ag[i + 1], ab[i + 1],
                                     An + (3 + i) * 256, Bn + (3 + i) * 256, 64, 64);
    conv1x1_bn_kernel<<<dim3(64, 1, BATCH), 256>>>(
        buf2, aw[0], brb, 256, An + 256, Bn + 256, p1 + 32768, p2 + 32768);
    finalize_kernel<<<64, 128>>>(p1 + 32768, p2 + 32768, ag[0], ab[0],
                                 An + 2 * 256, Bn + 2 * 256, 64, 256);

    // fused qkv (fp16 fragment emission) + pos
    qkv_kernel<<<dim3(64, 1, 16), 256>>>(brb, wq, bq, wk, bk, wv, bv,
                                         qb, kfb, vfb, An, Bn);
    pos_kernel<<<(64 * NPIX + 255) / 256, 256>>>(rel_h, rel_w);

    // fp16 flash attention (no smem) -> concat output
    flash_mma_kernel<<<dim3(32, BATCH, 4), 256>>>(qb, kfb, vfb, (float*)d_out);
}